// round 10
// baseline (speedup 1.0000x reference)
#include <cuda_runtime.h>
#include <cuda_bf16.h>
#include <cstdint>

// Problem constants
#define Bn 16
#define Fc 64
#define Ec 16
#define Hh 64
#define Ww 64
#define HW (Hh * Ww)

// Scratch (device globals: allocation-free rule)
__device__ float g_partials[Bn * 32 * 16 * 64];          // fuse partial sums
__device__ __align__(16) uint32_t g_xhi[Bn * HW * 32];   // state bf16-hi [b][pix][ci2]
__device__ __align__(16) uint32_t g_xlo[Bn * HW * 32];   // state bf16-lo
__device__ __align__(16) uint32_t g_x2hi[Bn * HW * 32];  // relu(conv1) bf16-hi
__device__ __align__(16) uint32_t g_x2lo[Bn * HW * 32];  // relu(conv1) bf16-lo
__device__ __align__(16) uint8_t  g_wtile[9 * 16384];    // conv1 W swizzled [tap][part][co][ci]
__device__ __align__(16) uint8_t  g_wtile2[9 * 4096];    // conv2 W swizzled
__device__ __align__(16) uint8_t  g_wtile3[16384];       // c3_w swizzled [part][o][f]

// ---------------------------------------------------------------------------
// mma.sync + ldmatrix + cp.async (baseline PTX, legal at compute_103)
// ---------------------------------------------------------------------------
__device__ __forceinline__ void mma16816(float* d, const uint32_t* a, const uint32_t* b)
{
    asm volatile(
        "mma.sync.aligned.m16n8k16.row.col.f32.bf16.bf16.f32 "
        "{%0,%1,%2,%3}, {%4,%5,%6,%7}, {%8,%9}, {%0,%1,%2,%3};"
        : "+f"(d[0]), "+f"(d[1]), "+f"(d[2]), "+f"(d[3])
        : "r"(a[0]), "r"(a[1]), "r"(a[2]), "r"(a[3]), "r"(b[0]), "r"(b[1]));
}

__device__ __forceinline__ void ldsm4(uint32_t* r, uint32_t addr)
{
    asm volatile("ldmatrix.sync.aligned.m8n8.x4.shared.b16 {%0,%1,%2,%3}, [%4];"
                 : "=r"(r[0]), "=r"(r[1]), "=r"(r[2]), "=r"(r[3]) : "r"(addr));
}

__device__ __forceinline__ void cp16(uint32_t dst, const void* src)
{
    asm volatile("cp.async.cg.shared.global [%0], [%1], 16;" :: "r"(dst), "l"(src));
}
__device__ __forceinline__ void cp_commit()
{
    asm volatile("cp.async.commit_group;" ::: "memory");
}
template <int N>
__device__ __forceinline__ void cp_wait()
{
    asm volatile("cp.async.wait_group %0;" :: "n"(N) : "memory");
}

__device__ __forceinline__ uint32_t smem_u32(const void* p)
{
    uint32_t a;
    asm("{ .reg .u64 t; cvta.to.shared.u64 t, %1; cvt.u32.u64 %0, t; }" : "=r"(a) : "l"(p));
    return a;
}

__device__ __forceinline__ uint32_t pack_bf16x2(float v0, float v1)
{
    __nv_bfloat16 h0 = __float2bfloat16(v0);
    __nv_bfloat16 h1 = __float2bfloat16(v1);
    return ((uint32_t)__bfloat16_as_ushort(h1) << 16) | __bfloat16_as_ushort(h0);
}

// ---------------------------------------------------------------------------
// Weight prep (all three weight sets in one kernel; swizzle q ^= row&7)
// blocks 0..71: conv1 W; 72..89: conv2 W; 90..97: c3_w
// ---------------------------------------------------------------------------
__global__ __launch_bounds__(256) void wprep_all_kernel(
    const float* __restrict__ w1, const float* __restrict__ w2,
    const float* __restrict__ w3)
{
    int bi = blockIdx.x;
    if (bi < 72) {
        int idx = bi * 256 + threadIdx.x;          // (tap, co64, ci-pair)
        int tap = idx >> 11;
        int rem = idx & 2047;
        int co = rem >> 5, ci2 = rem & 31;
        float v0 = w1[(co * 64 + 2 * ci2) * 9 + tap];
        float v1 = w1[(co * 64 + 2 * ci2 + 1) * 9 + tap];
        __nv_bfloat16 h0 = __float2bfloat16(v0);
        __nv_bfloat16 h1 = __float2bfloat16(v1);
        int q = ci2 >> 2, wd = ci2 & 3;
        int sw = ((q ^ (co & 7)) << 4) + wd * 4;
        *(uint32_t*)(g_wtile + tap * 16384 + co * 128 + sw) =
            ((uint32_t)__bfloat16_as_ushort(h1) << 16) | __bfloat16_as_ushort(h0);
        *(uint32_t*)(g_wtile + tap * 16384 + 8192 + co * 128 + sw) =
            pack_bf16x2(v0 - __bfloat162float(h0), v1 - __bfloat162float(h1));
    } else if (bi < 90) {
        int idx = (bi - 72) * 256 + threadIdx.x;   // (tap, co16, ci-pair)
        if (idx >= 9 * 512) return;
        int tap = idx >> 9;
        int rem = idx & 511;
        int co = rem >> 5, ci2 = rem & 31;
        float v0 = w2[(co * 64 + 2 * ci2) * 9 + tap];
        float v1 = w2[(co * 64 + 2 * ci2 + 1) * 9 + tap];
        __nv_bfloat16 h0 = __float2bfloat16(v0);
        __nv_bfloat16 h1 = __float2bfloat16(v1);
        int q = ci2 >> 2, wd = ci2 & 3;
        int sw = ((q ^ (co & 7)) << 4) + wd * 4;
        *(uint32_t*)(g_wtile2 + tap * 4096 + co * 128 + sw) =
            ((uint32_t)__bfloat16_as_ushort(h1) << 16) | __bfloat16_as_ushort(h0);
        *(uint32_t*)(g_wtile2 + tap * 4096 + 2048 + co * 128 + sw) =
            pack_bf16x2(v0 - __bfloat162float(h0), v1 - __bfloat162float(h1));
    } else {
        int idx = (bi - 90) * 256 + threadIdx.x;   // (o64, f-pair)
        if (idx >= 2048) return;
        int o = idx >> 5, f2 = idx & 31;
        float v0 = w3[o * 64 + 2 * f2];
        float v1 = w3[o * 64 + 2 * f2 + 1];
        __nv_bfloat16 h0 = __float2bfloat16(v0);
        __nv_bfloat16 h1 = __float2bfloat16(v1);
        int q = f2 >> 2, wd = f2 & 3;
        int sw = ((q ^ (o & 7)) << 4) + wd * 4;
        *(uint32_t*)(g_wtile3 + o * 128 + sw) =
            ((uint32_t)__bfloat16_as_ushort(h1) << 16) | __bfloat16_as_ushort(h0);
        *(uint32_t*)(g_wtile3 + 8192 + o * 128 + sw) =
            pack_bf16x2(v0 - __bfloat162float(h0), v1 - __bfloat162float(h1));
    }
}

// ---------------------------------------------------------------------------
// Prep: state NCHW fp32 -> [b][pix][ci] bf16 hi/lo (pixel-major, 128B/pixel)
// ---------------------------------------------------------------------------
__global__ __launch_bounds__(256) void xprep_kernel(const float* __restrict__ state)
{
    __shared__ float s[64 * 65];
    int b = blockIdx.x >> 6, y = blockIdx.x & 63;
    int tid = threadIdx.x;
#pragma unroll
    for (int k = 0; k < 16; k++) {
        int idx = tid + k * 256;
        int ci = idx >> 6, x = idx & 63;
        s[ci * 65 + x] = state[((long)(b * 64 + ci) * 64 + y) * 64 + x];
    }
    __syncthreads();
#pragma unroll
    for (int k = 0; k < 8; k++) {
        int idx = tid + k * 256;
        int x = idx >> 5, j = idx & 31;
        float v0 = s[(2 * j) * 65 + x];
        float v1 = s[(2 * j + 1) * 65 + x];
        __nv_bfloat16 h0 = __float2bfloat16(v0);
        __nv_bfloat16 h1 = __float2bfloat16(v1);
        long o = ((long)b * 4096 + y * 64 + x) * 32 + j;
        g_xhi[o] = ((uint32_t)__bfloat16_as_ushort(h1) << 16) | __bfloat16_as_ushort(h0);
        g_xlo[o] = pack_bf16x2(v0 - __bfloat162float(h0), v1 - __bfloat162float(h1));
    }
}

// ---------------------------------------------------------------------------
// Conv smem layouts
// ---------------------------------------------------------------------------
#define AHALO_PIX 264            /* 4 * 66 */
#define AH_OFF 0
#define AL_OFF 33792             /* 264*128 */
#define B1_OFF 67584             /* 2 x 16KB double buffer */
#define BIAS1_OFF (B1_OFF + 32768)             /* 100352 */
#define CONV1_SMEM (BIAS1_OFF + 256)           /* 100608 */
#define B2_OFF 67584
#define BIAS2_OFF (B2_OFF + 36864)             /* 104448 */
#define CONV2_SMEM (BIAS2_OFF + 64)            /* 104512 */

template <int NT>
__device__ __forceinline__ void stage_halo(
    char* smem, const uint4* xh4, const uint4* xl4, int b, int y0, int tid)
{
    for (int p = tid; p < AHALO_PIX; p += NT) {
        int r = p / 66, c = p - r * 66;
        int y = y0 - 1 + r;
        int x = c - 1;
        bool ok = ((unsigned)y < 64u) && ((unsigned)x < 64u);
        long pix8 = ((long)b * 4096 + y * 64 + x) * 8;
        char* dh = smem + AH_OFF + p * 128;
        char* dl = smem + AL_OFF + p * 128;
        int key = p & 7;
#pragma unroll
        for (int q = 0; q < 8; q++) {
            uint4 vh = make_uint4(0, 0, 0, 0), vl = make_uint4(0, 0, 0, 0);
            if (ok) { vh = xh4[pix8 + q]; vl = xl4[pix8 + q]; }
            int sw = (q ^ key) << 4;
            *(uint4*)(dh + sw) = vh;
            *(uint4*)(dl + sw) = vl;
        }
    }
}

// ---------------------------------------------------------------------------
// conv1: 256 threads, 8 warps (wm 0..3 x wn 0..1), warp tile 32x32.
// B double-buffered via cp.async (tap stream); 2 CTAs/SM.
// ---------------------------------------------------------------------------
__global__ __launch_bounds__(256) void conv1_mma_kernel(const float* __restrict__ bias)
{
    extern __shared__ char smem[];
    const uint32_t sb = smem_u32(smem);
    const int tid = threadIdx.x;
    const int w8 = tid >> 5;
    const int wm = w8 & 3;
    const int wn = w8 >> 2;
    const int l = tid & 31;
    const int b = blockIdx.x >> 5;
    const int y0 = (blockIdx.x & 31) * 2;

    if (tid < 64) *(float*)(smem + BIAS1_OFF + tid * 4) = bias[tid];

    // prefetch B tap0 -> buf0, tap1 -> buf1 (groups 0, 1)
#pragma unroll
    for (int i = 0; i < 4; i++) {
        int idx = tid + i * 256;
        cp16(sb + B1_OFF + idx * 16, g_wtile + idx * 16);
    }
    cp_commit();
#pragma unroll
    for (int i = 0; i < 4; i++) {
        int idx = tid + i * 256;
        cp16(sb + B1_OFF + 16384 + idx * 16, g_wtile + 16384 + idx * 16);
    }
    cp_commit();

    stage_halo<256>(smem, (const uint4*)g_xhi, (const uint4*)g_xlo, b, y0, tid);

    float d[2][4][4];
#pragma unroll
    for (int mt = 0; mt < 2; mt++)
#pragma unroll
        for (int nb = 0; nb < 4; nb++)
#pragma unroll
            for (int j = 0; j < 4; j++) d[mt][nb][j] = 0.f;

    const int lane7 = l & 7;
    const int hi16 = (l >> 4) & 1;
    int ax[2], aly[2];
#pragma unroll
    for (int mt = 0; mt < 2; mt++) {
        int mrow = wm * 32 + mt * 16 + (l & 8) + lane7;
        ax[mt] = mrow & 63;
        aly[mt] = mrow >> 6;
    }
    const int brow = ((l >> 4) & 1) * 8 + lane7;
    const int bcb = (l >> 3) & 1;

#pragma unroll
    for (int tap = 0; tap < 9; tap++) {
        if (tap < 8) cp_wait<1>(); else cp_wait<0>();
        __syncthreads();

        const int dy = tap / 3 - 1;
        const int dx = tap % 3 - 1;
        uint32_t abase[2];
        int akey[2];
#pragma unroll
        for (int mt = 0; mt < 2; mt++) {
            int p = (aly[mt] + dy + 1) * 66 + ax[mt] + dx + 1;
            akey[mt] = p & 7;
            abase[mt] = sb + p * 128;
        }
        const uint32_t btap = sb + B1_OFF + (tap & 1) * 16384;
#pragma unroll
        for (int kb = 0; kb < 4; kb++) {
            uint32_t ah[2][4], al[2][4];
#pragma unroll
            for (int mt = 0; mt < 2; mt++) {
                int chunk = kb * 2 + hi16;
                uint32_t sw = (uint32_t)((chunk ^ akey[mt]) << 4);
                ldsm4(ah[mt], abase[mt] + sw);
                ldsm4(al[mt], abase[mt] + AL_OFF + sw);
            }
#pragma unroll
            for (int nbl = 0; nbl < 2; nbl++) {
                int nbp = wn * 2 + nbl;
                int n = nbp * 16 + brow;
                uint32_t baddr = btap + n * 128 +
                                 (uint32_t)((((kb * 2 + bcb) ^ (n & 7))) << 4);
                uint32_t bh[4], bl[4];
                ldsm4(bh, baddr);
                ldsm4(bl, baddr + 8192);
#pragma unroll
                for (int mt = 0; mt < 2; mt++) {
                    mma16816(d[mt][2 * nbl], ah[mt], bh);
                    mma16816(d[mt][2 * nbl], al[mt], bh);
                    mma16816(d[mt][2 * nbl], ah[mt], bl);
                    mma16816(d[mt][2 * nbl + 1], ah[mt], bh + 2);
                    mma16816(d[mt][2 * nbl + 1], al[mt], bh + 2);
                    mma16816(d[mt][2 * nbl + 1], ah[mt], bl + 2);
                }
            }
        }
        __syncthreads();
        if (tap + 2 <= 8) {
            const uint8_t* src = g_wtile + (tap + 2) * 16384;
            uint32_t dst = sb + B1_OFF + (tap & 1) * 16384;
#pragma unroll
            for (int i = 0; i < 4; i++) {
                int idx = tid + i * 256;
                cp16(dst + idx * 16, src + idx * 16);
            }
            cp_commit();
        }
    }

    // epilogue: bias+relu -> bf16 hi/lo pixel-major
    const int lr = l >> 2;
    const int lc2 = l & 3;
#pragma unroll
    for (int mt = 0; mt < 2; mt++) {
#pragma unroll
        for (int nbl = 0; nbl < 4; nbl++) {
            int nb = wn * 4 + nbl;
            float b0 = *(const float*)(smem + BIAS1_OFF + (nb * 8 + lc2 * 2) * 4);
            float b1 = *(const float*)(smem + BIAS1_OFF + (nb * 8 + lc2 * 2 + 1) * 4);
#pragma unroll
            for (int row = 0; row < 2; row++) {
                int m = wm * 32 + mt * 16 + lr + row * 8;
                float v0 = fmaxf(d[mt][nbl][row * 2 + 0] + b0, 0.f);
                float v1 = fmaxf(d[mt][nbl][row * 2 + 1] + b1, 0.f);
                __nv_bfloat16 h0 = __float2bfloat16(v0);
                __nv_bfloat16 h1 = __float2bfloat16(v1);
                long o = ((long)b * 4096 + y0 * 64 + m) * 32 + nb * 4 + lc2;
                g_x2hi[o] = ((uint32_t)__bfloat16_as_ushort(h1) << 16) |
                            __bfloat16_as_ushort(h0);
                g_x2lo[o] = pack_bf16x2(v0 - __bfloat162float(h0),
                                        v1 - __bfloat162float(h1));
            }
        }
    }
}

// ---------------------------------------------------------------------------
// conv2: 256 threads, 8 warps, warp tile M=16 x N=16; sigmoid into d_out.
// 2 CTAs/SM (104.5KB smem) -> 16 warps/SM.
// ---------------------------------------------------------------------------
__global__ __launch_bounds__(256) void conv2_mma_kernel(
    const float* __restrict__ bias, float* __restrict__ attn)
{
    extern __shared__ char smem[];
    const uint32_t sb = smem_u32(smem);
    const int tid = threadIdx.x;
    const int w8 = tid >> 5;
    const int l = tid & 31;
    const int b = blockIdx.x >> 5;
    const int y0 = (blockIdx.x & 31) * 2;

    if (tid < 16) *(float*)(smem + BIAS2_OFF + tid * 4) = bias[tid];

    {
        const uint4* wsrc = (const uint4*)g_wtile2;
        uint4* dst = (uint4*)(smem + B2_OFF);
#pragma unroll
        for (int i = 0; i < 9; i++) dst[tid + i * 256] = wsrc[tid + i * 256];
    }
    stage_halo<256>(smem, (const uint4*)g_x2hi, (const uint4*)g_x2lo, b, y0, tid);
    __syncthreads();

    float d[2][4];
#pragma unroll
    for (int nb = 0; nb < 2; nb++)
#pragma unroll
        for (int j = 0; j < 4; j++) d[nb][j] = 0.f;

    const int lane7 = l & 7;
    const int hi16 = (l >> 4) & 1;
    const int mrow = w8 * 16 + (l & 8) + lane7;
    const int ax = mrow & 63;
    const int aly = mrow >> 6;
    const int brow = ((l >> 4) & 1) * 8 + lane7;
    const int bcb = (l >> 3) & 1;

#pragma unroll
    for (int tap = 0; tap < 9; tap++) {
        const int dy = tap / 3 - 1;
        const int dx = tap % 3 - 1;
        int p = (aly + dy + 1) * 66 + ax + dx + 1;
        const int akey = p & 7;
        const uint32_t abase = sb + p * 128;
        const uint32_t btap = sb + B2_OFF + tap * 4096;
#pragma unroll
        for (int kb = 0; kb < 4; kb++) {
            uint32_t ah[4], al[4];
            {
                int chunk = kb * 2 + hi16;
                uint32_t sw = (uint32_t)((chunk ^ akey) << 4);
                ldsm4(ah, abase + sw);
                ldsm4(al, abase + AL_OFF + sw);
            }
            {
                int n = brow;
                uint32_t baddr = btap + n * 128 +
                                 (uint32_t)((((kb * 2 + bcb) ^ (n & 7))) << 4);
                uint32_t bh[4], bl[4];
                ldsm4(bh, baddr);
                ldsm4(bl, baddr + 2048);
                mma16816(d[0], ah, bh);
                mma16816(d[0], al, bh);
                mma16816(d[0], ah, bl);
                mma16816(d[1], ah, bh + 2);
                mma16816(d[1], al, bh + 2);
                mma16816(d[1], ah, bl + 2);
            }
        }
    }

    // epilogue: bias + sigmoid -> attn NCHW fp32 (straight into d_out)
    const int lr = l >> 2;
    const int lc = (l & 3) * 2;
#pragma unroll
    for (int nb = 0; nb < 2; nb++) {
#pragma unroll
        for (int j = 0; j < 4; j++) {
            int n = nb * 8 + lc + (j & 1);
            int m = w8 * 16 + lr + ((j >> 1) * 8);
            float v = d[nb][j] + *(const float*)(smem + BIAS2_OFF + n * 4);
            v = 1.f / (1.f + __expf(-v));
            attn[((long)(b * 16 + n)) * 4096 + y0 * 64 + m] = v;
        }
    }
}

// ---------------------------------------------------------------------------
// fuse: cs-GEMM on HMMA (state bf16 hi/lo x c3_w) + relu-reduction partials.
// block = (b, 128-pixel chunk); 256 threads, warp tile 32x32.
// ---------------------------------------------------------------------------
#define F_AH 0
#define F_AL 16384
#define F_B  32768               /* hi 8K, lo 8K */
#define F_CS 49152               /* 128 x 68 fp32 = 34816 */
#define F_ATT 83968              /* 16 x 128 fp32 = 8192 */
#define FUSE_SMEM 92160

__global__ __launch_bounds__(256) void fuse_kernel(
    const float* __restrict__ attn, const float* __restrict__ c3_b)
{
    extern __shared__ char smem[];
    const uint32_t sb = smem_u32(smem);
    float* cs_s = (float*)(smem + F_CS);
    float* attn_s = (float*)(smem + F_ATT);

    const int tid = threadIdx.x;
    const int w8 = tid >> 5;
    const int wm = w8 & 3;
    const int wn = w8 >> 2;
    const int l = tid & 31;
    const int b = blockIdx.x >> 5;
    const int chunk = blockIdx.x & 31;
    const int pbase = chunk * 128;

    // stage A (128 pixels of state hi/lo, swizzled), B (c3_w tiles), attn
    {
        const uint8_t* srch = (const uint8_t*)g_xhi + ((long)b * 4096 + pbase) * 128;
        const uint8_t* srcl = (const uint8_t*)g_xlo + ((long)b * 4096 + pbase) * 128;
        // 128 pixels x 8 chunks = 1024 16B units; each iteration covers 256
#pragma unroll
        for (int i = 0; i < 4; i++) {
            int idx = tid + i * 256;       // (pp, q)
            int pp = idx >> 3, q = idx & 7;
            uint32_t sw = (uint32_t)(pp * 128 + ((q ^ (pp & 7)) << 4));
            cp16(sb + F_AH + sw, srch + idx * 16);
            cp16(sb + F_AL + sw, srcl + idx * 16);
        }
#pragma unroll
        for (int i = 0; i < 4; i++) {
            int idx = tid + i * 256;
            cp16(sb + F_B + idx * 16, g_wtile3 + idx * 16);
        }
        // attn chunk: 16 e x 128 pp floats = 512 x 16B
#pragma unroll
        for (int i = 0; i < 2; i++) {
            int idx = tid + i * 256;       // 16B unit: (e, pp/4)
            int e = idx >> 5, p4 = idx & 31;
            cp16(sb + F_ATT + idx * 16,
                 attn + ((long)b * 16 + e) * HW + pbase + p4 * 4);
        }
        cp_commit();
        cp_wait<0>();
        __syncthreads();
    }

    // cs-GEMM: D[128 pix][64 o] via 3-term bf16 HMMA
    float d[2][4][4];
#pragma unroll
    for (int mt = 0; mt < 2; mt++)
#pragma unroll
        for (int nb = 0; nb < 4; nb++)
#pragma unroll
            for (int j = 0; j < 4; j++) d[mt][nb][j] = 0.f;

    const int lane7 = l & 7;
    const int hi16 = (l >> 4) & 1;
    const int brow = ((l >> 4) & 1) * 8 + lane7;
    const int bcb = (l >> 3) & 1;

#pragma unroll
    for (int kb = 0; kb < 4; kb++) {
        uint32_t ah[2][4], al[2][4];
#pragma unroll
        for (int mt = 0; mt < 2; mt++) {
            int pp = wm * 32 + mt * 16 + (l & 8) + lane7;
            int chunkq = kb * 2 + hi16;
            uint32_t sw = (uint32_t)(pp * 128 + ((chunkq ^ (pp & 7)) << 4));
            ldsm4(ah[mt], sb + F_AH + sw);
            ldsm4(al[mt], sb + F_AL + sw);
        }
#pragma unroll
        for (int nbl = 0; nbl < 2; nbl++) {
            int nbp = wn * 2 + nbl;
            int n = nbp * 16 + brow;
            uint32_t baddr = sb + F_B + n * 128 +
                             (uint32_t)((((kb * 2 + bcb) ^ (n & 7))) << 4);
            uint32_t bh[4], bl[4];
            ldsm4(bh, baddr);
            ldsm4(bl, baddr + 8192);
#pragma unroll
            for (int mt = 0; mt < 2; mt++) {
                mma16816(d[mt][2 * nbl], ah[mt], bh);
                mma16816(d[mt][2 * nbl], al[mt], bh);
                mma16816(d[mt][2 * nbl], ah[mt], bl);
                mma16816(d[mt][2 * nbl + 1], ah[mt], bh + 2);
                mma16816(d[mt][2 * nbl + 1], al[mt], bh + 2);
                mma16816(d[mt][2 * nbl + 1], ah[mt], bl + 2);
            }
        }
    }

    // write cs fragments to smem [pp][o] pitch 68
    {
        const int lr = l >> 2;
        const int lc = (l & 3) * 2;
#pragma unroll
        for (int mt = 0; mt < 2; mt++) {
#pragma unroll
            for (int nbl = 0; nbl < 4; nbl++) {
                int nb = wn * 4 + nbl;
#pragma unroll
                for (int row = 0; row < 2; row++) {
                    int m = wm * 32 + mt * 16 + lr + row * 8;
                    int n = nb * 8 + lc;
                    float2 v = make_float2(d[mt][nbl][row * 2 + 0],
                                           d[mt][nbl][row * 2 + 1]);
                    *(float2*)(cs_s + m * 68 + n) = v;
                }
            }
        }
    }
    __syncthreads();

    // relu-reduction: thread (e, oq) sums 4 o's over 128 pixels
    {
        const int e = tid >> 4;
        const int oq = tid & 15;
        const float4 bias = ((const float4*)c3_b)[oq];
        float4 acc = make_float4(0.f, 0.f, 0.f, 0.f);
        const float* arow = attn_s + e * 128;
#pragma unroll 4
        for (int pp = 0; pp < 128; pp++) {
            float a = arow[pp];
            float4 cv = *(const float4*)(cs_s + pp * 68 + oq * 4);
            acc.x += fmaxf(fmaf(a, cv.x, bias.x), 0.f);
            acc.y += fmaxf(fmaf(a, cv.y, bias.y), 0.f);
            acc.z += fmaxf(fmaf(a, cv.z, bias.z), 0.f);
            acc.w += fmaxf(fmaf(a, cv.w, bias.w), 0.f);
        }
        float4* po = (float4*)(g_partials + ((long)(b * 32 + chunk)) * 1024 + e * 64 + oq * 4);
        *po = acc;
    }
}

__global__ __launch_bounds__(256) void reduce_kernel(
    const float* __restrict__ c3_b, float* __restrict__ out)
{
    int gid = blockIdx.x * 256 + threadIdx.x;
    int o = gid & 63;
    float sum = 260.f * fmaxf(c3_b[o], 0.f);
    int b = gid >> 10;
    int eo = gid & 1023;
    const float* p = g_partials + (long)b * 32 * 1024 + eo;
#pragma unroll
    for (int c = 0; c < 32; c++) sum += p[c * 1024];
    out[gid] = sum * (1.f / 4356.f);
}

// ---------------------------------------------------------------------------
extern "C" void kernel_launch(void* const* d_in, const int* in_sizes, int n_in,
                              void* d_out, int out_size)
{
    const float* state = (const float*)d_in[0];
    const float* pre_w = (const float*)d_in[1];
    const float* pre_b = (const float*)d_in[2];
    const float* attn_w = (const float*)d_in[3];
    const float* attn_b = (const float*)d_in[4];
    const float* c3_w = (const float*)d_in[5];
    const float* c3_b = (const float*)d_in[6];

    float* out = (float*)d_out;
    float* attn = out + Bn * Ec * Fc;

    cudaFuncSetAttribute(fuse_kernel, cudaFuncAttributeMaxDynamicSharedMemorySize,
                         FUSE_SMEM);
    cudaFuncSetAttribute(conv1_mma_kernel, cudaFuncAttributeMaxDynamicSharedMemorySize,
                         CONV1_SMEM);
    cudaFuncSetAttribute(conv2_mma_kernel, cudaFuncAttributeMaxDynamicSharedMemorySize,
                         CONV2_SMEM);

    // prep: all weights (one kernel) + state to bf16 hi/lo
    wprep_all_kernel<<<98, 256>>>(pre_w, attn_w, c3_w);
    xprep_kernel<<<Bn * 64, 256>>>(state);
    // conv1 on HMMA: B double-buffered via cp.async, 2 CTAs/SM
    conv1_mma_kernel<<<Bn * 32, 256, CONV1_SMEM>>>(pre_b);
    // conv2 on HMMA: 256 threads, warp tile M=16, 2 CTAs/SM
    conv2_mma_kernel<<<Bn * 32, 256, CONV2_SMEM>>>(attn_b, attn);
    // fuse: cs-GEMM on HMMA + relu-reduction partials
    fuse_kernel<<<Bn * 32, 256, FUSE_SMEM>>>(attn, c3_b);
    // final reduce + pad term
    reduce_kernel<<<64, 256>>>(c3_b, out);
}

// round 11
// speedup vs baseline: 1.2071x; 1.2071x over previous
#include <cuda_runtime.h>
#include <cuda_bf16.h>
#include <cuda_fp16.h>
#include <cstdint>

// Problem constants
#define Bn 16
#define Fc 64
#define Ec 16
#define Hh 64
#define Ww 64
#define HW (Hh * Ww)

// Scratch (device globals: allocation-free rule)
__device__ float g_partials[Bn * 32 * 16 * 64];          // fuse partial sums
__device__ __align__(16) uint32_t g_xhi[Bn * HW * 32];   // state bf16-hi [b][pix][ci2]
__device__ __align__(16) uint32_t g_xlo[Bn * HW * 32];   // state bf16-lo
__device__ __align__(16) uint32_t g_x2[Bn * HW * 32];    // relu(conv1) fp16 [b][pix][ci2]
__device__ __align__(16) uint8_t  g_wtile[9 * 16384];    // conv1 W bf16 hi/lo swizzled
__device__ __align__(16) uint8_t  g_wtile2[9 * 2048];    // conv2 W fp16 swizzled
__device__ __align__(16) uint8_t  g_wtile3[16384];       // c3_w bf16 hi/lo swizzled

// ---------------------------------------------------------------------------
// mma.sync + ldmatrix + cp.async (baseline PTX, legal at compute_103)
// ---------------------------------------------------------------------------
__device__ __forceinline__ void mma16816(float* d, const uint32_t* a, const uint32_t* b)
{
    asm volatile(
        "mma.sync.aligned.m16n8k16.row.col.f32.bf16.bf16.f32 "
        "{%0,%1,%2,%3}, {%4,%5,%6,%7}, {%8,%9}, {%0,%1,%2,%3};"
        : "+f"(d[0]), "+f"(d[1]), "+f"(d[2]), "+f"(d[3])
        : "r"(a[0]), "r"(a[1]), "r"(a[2]), "r"(a[3]), "r"(b[0]), "r"(b[1]));
}

__device__ __forceinline__ void mma16816h(float* d, const uint32_t* a, const uint32_t* b)
{
    asm volatile(
        "mma.sync.aligned.m16n8k16.row.col.f32.f16.f16.f32 "
        "{%0,%1,%2,%3}, {%4,%5,%6,%7}, {%8,%9}, {%0,%1,%2,%3};"
        : "+f"(d[0]), "+f"(d[1]), "+f"(d[2]), "+f"(d[3])
        : "r"(a[0]), "r"(a[1]), "r"(a[2]), "r"(a[3]), "r"(b[0]), "r"(b[1]));
}

__device__ __forceinline__ void ldsm4(uint32_t* r, uint32_t addr)
{
    asm volatile("ldmatrix.sync.aligned.m8n8.x4.shared.b16 {%0,%1,%2,%3}, [%4];"
                 : "=r"(r[0]), "=r"(r[1]), "=r"(r[2]), "=r"(r[3]) : "r"(addr));
}

__device__ __forceinline__ void cp16(uint32_t dst, const void* src)
{
    asm volatile("cp.async.cg.shared.global [%0], [%1], 16;" :: "r"(dst), "l"(src));
}
__device__ __forceinline__ void cp_commit()
{
    asm volatile("cp.async.commit_group;" ::: "memory");
}
template <int N>
__device__ __forceinline__ void cp_wait()
{
    asm volatile("cp.async.wait_group %0;" :: "n"(N) : "memory");
}

__device__ __forceinline__ uint32_t smem_u32(const void* p)
{
    uint32_t a;
    asm("{ .reg .u64 t; cvta.to.shared.u64 t, %1; cvt.u32.u64 %0, t; }" : "=r"(a) : "l"(p));
    return a;
}

__device__ __forceinline__ uint32_t pack_bf16x2(float v0, float v1)
{
    __nv_bfloat16 h0 = __float2bfloat16(v0);
    __nv_bfloat16 h1 = __float2bfloat16(v1);
    return ((uint32_t)__bfloat16_as_ushort(h1) << 16) | __bfloat16_as_ushort(h0);
}

__device__ __forceinline__ uint32_t pack_f16x2(float v0, float v1)
{
    __half2 h = __floats2half2_rn(v0, v1);
    return *(uint32_t*)&h;
}

// ---------------------------------------------------------------------------
// Weight prep: conv1 (bf16 hi/lo), conv2 (fp16 single), c3_w (bf16 hi/lo)
// blocks 0..71: conv1; 72..89: conv2; 90..97: c3_w   (swizzle q ^= row&7)
// ---------------------------------------------------------------------------
__global__ __launch_bounds__(256) void wprep_all_kernel(
    const float* __restrict__ w1, const float* __restrict__ w2,
    const float* __restrict__ w3)
{
    int bi = blockIdx.x;
    if (bi < 72) {
        int idx = bi * 256 + threadIdx.x;          // (tap, co64, ci-pair)
        int tap = idx >> 11;
        int rem = idx & 2047;
        int co = rem >> 5, ci2 = rem & 31;
        float v0 = w1[(co * 64 + 2 * ci2) * 9 + tap];
        float v1 = w1[(co * 64 + 2 * ci2 + 1) * 9 + tap];
        __nv_bfloat16 h0 = __float2bfloat16(v0);
        __nv_bfloat16 h1 = __float2bfloat16(v1);
        int q = ci2 >> 2, wd = ci2 & 3;
        int sw = ((q ^ (co & 7)) << 4) + wd * 4;
        *(uint32_t*)(g_wtile + tap * 16384 + co * 128 + sw) =
            ((uint32_t)__bfloat16_as_ushort(h1) << 16) | __bfloat16_as_ushort(h0);
        *(uint32_t*)(g_wtile + tap * 16384 + 8192 + co * 128 + sw) =
            pack_bf16x2(v0 - __bfloat162float(h0), v1 - __bfloat162float(h1));
    } else if (bi < 90) {
        int idx = (bi - 72) * 256 + threadIdx.x;   // (tap, co16, ci-pair)
        if (idx >= 9 * 512) return;
        int tap = idx >> 9;
        int rem = idx & 511;
        int co = rem >> 5, ci2 = rem & 31;
        float v0 = w2[(co * 64 + 2 * ci2) * 9 + tap];
        float v1 = w2[(co * 64 + 2 * ci2 + 1) * 9 + tap];
        int q = ci2 >> 2, wd = ci2 & 3;
        int sw = ((q ^ (co & 7)) << 4) + wd * 4;
        *(uint32_t*)(g_wtile2 + tap * 2048 + co * 128 + sw) = pack_f16x2(v0, v1);
    } else {
        int idx = (bi - 90) * 256 + threadIdx.x;   // (o64, f-pair)
        if (idx >= 2048) return;
        int o = idx >> 5, f2 = idx & 31;
        float v0 = w3[o * 64 + 2 * f2];
        float v1 = w3[o * 64 + 2 * f2 + 1];
        __nv_bfloat16 h0 = __float2bfloat16(v0);
        __nv_bfloat16 h1 = __float2bfloat16(v1);
        int q = f2 >> 2, wd = f2 & 3;
        int sw = ((q ^ (o & 7)) << 4) + wd * 4;
        *(uint32_t*)(g_wtile3 + o * 128 + sw) =
            ((uint32_t)__bfloat16_as_ushort(h1) << 16) | __bfloat16_as_ushort(h0);
        *(uint32_t*)(g_wtile3 + 8192 + o * 128 + sw) =
            pack_bf16x2(v0 - __bfloat162float(h0), v1 - __bfloat162float(h1));
    }
}

// ---------------------------------------------------------------------------
// Prep: state NCHW fp32 -> [b][pix][ci] bf16 hi/lo (pixel-major, 128B/pixel)
// ---------------------------------------------------------------------------
__global__ __launch_bounds__(256) void xprep_kernel(const float* __restrict__ state)
{
    __shared__ float s[64 * 65];
    int b = blockIdx.x >> 6, y = blockIdx.x & 63;
    int tid = threadIdx.x;
#pragma unroll
    for (int k = 0; k < 16; k++) {
        int idx = tid + k * 256;
        int ci = idx >> 6, x = idx & 63;
        s[ci * 65 + x] = state[((long)(b * 64 + ci) * 64 + y) * 64 + x];
    }
    __syncthreads();
#pragma unroll
    for (int k = 0; k < 8; k++) {
        int idx = tid + k * 256;
        int x = idx >> 5, j = idx & 31;
        float v0 = s[(2 * j) * 65 + x];
        float v1 = s[(2 * j + 1) * 65 + x];
        __nv_bfloat16 h0 = __float2bfloat16(v0);
        __nv_bfloat16 h1 = __float2bfloat16(v1);
        long o = ((long)b * 4096 + y * 64 + x) * 32 + j;
        g_xhi[o] = ((uint32_t)__bfloat16_as_ushort(h1) << 16) | __bfloat16_as_ushort(h0);
        g_xlo[o] = pack_bf16x2(v0 - __bfloat162float(h0), v1 - __bfloat162float(h1));
    }
}

// ---------------------------------------------------------------------------
// Conv smem layouts
// ---------------------------------------------------------------------------
#define AHALO_PIX 264            /* 4 * 66 */
#define AH_OFF 0
#define AL_OFF 33792             /* 264*128 */
#define B1_OFF 67584             /* 2 x 16KB double buffer */
#define BIAS1_OFF (B1_OFF + 32768)             /* 100352 */
#define CONV1_SMEM (BIAS1_OFF + 256)           /* 100608 */
// conv2 (fp16 single): halo 33792 + B 9*2048 + bias
#define C2_B 33792
#define C2_BIAS (C2_B + 18432)                 /* 52224 */
#define CONV2_SMEM (C2_BIAS + 64)              /* 52288 */

// bf16 hi/lo halo (conv1)
__device__ __forceinline__ void stage_halo2(
    char* smem, const uint4* xh4, const uint4* xl4, int b, int y0, int tid)
{
    for (int p = tid; p < AHALO_PIX; p += 256) {
        int r = p / 66, c = p - r * 66;
        int y = y0 - 1 + r;
        int x = c - 1;
        bool ok = ((unsigned)y < 64u) && ((unsigned)x < 64u);
        long pix8 = ((long)b * 4096 + y * 64 + x) * 8;
        char* dh = smem + AH_OFF + p * 128;
        char* dl = smem + AL_OFF + p * 128;
        int key = p & 7;
#pragma unroll
        for (int q = 0; q < 8; q++) {
            uint4 vh = make_uint4(0, 0, 0, 0), vl = make_uint4(0, 0, 0, 0);
            if (ok) { vh = xh4[pix8 + q]; vl = xl4[pix8 + q]; }
            int sw = (q ^ key) << 4;
            *(uint4*)(dh + sw) = vh;
            *(uint4*)(dl + sw) = vl;
        }
    }
}

// ---------------------------------------------------------------------------
// conv1: 256 threads, 8 warps (wm 0..3 x wn 0..1), warp tile 32x32, bf16 3-term.
// B double-buffered via cp.async; 2 CTAs/SM. Epilogue emits x as fp16 single.
// ---------------------------------------------------------------------------
__global__ __launch_bounds__(256) void conv1_mma_kernel(const float* __restrict__ bias)
{
    extern __shared__ char smem[];
    const uint32_t sb = smem_u32(smem);
    const int tid = threadIdx.x;
    const int w8 = tid >> 5;
    const int wm = w8 & 3;
    const int wn = w8 >> 2;
    const int l = tid & 31;
    const int b = blockIdx.x >> 5;
    const int y0 = (blockIdx.x & 31) * 2;

    if (tid < 64) *(float*)(smem + BIAS1_OFF + tid * 4) = bias[tid];

    // prefetch B tap0 -> buf0, tap1 -> buf1
#pragma unroll
    for (int i = 0; i < 4; i++) {
        int idx = tid + i * 256;
        cp16(sb + B1_OFF + idx * 16, g_wtile + idx * 16);
    }
    cp_commit();
#pragma unroll
    for (int i = 0; i < 4; i++) {
        int idx = tid + i * 256;
        cp16(sb + B1_OFF + 16384 + idx * 16, g_wtile + 16384 + idx * 16);
    }
    cp_commit();

    stage_halo2(smem, (const uint4*)g_xhi, (const uint4*)g_xlo, b, y0, tid);

    float d[2][4][4];
#pragma unroll
    for (int mt = 0; mt < 2; mt++)
#pragma unroll
        for (int nb = 0; nb < 4; nb++)
#pragma unroll
            for (int j = 0; j < 4; j++) d[mt][nb][j] = 0.f;

    const int lane7 = l & 7;
    const int hi16 = (l >> 4) & 1;
    int ax[2], aly[2];
#pragma unroll
    for (int mt = 0; mt < 2; mt++) {
        int mrow = wm * 32 + mt * 16 + (l & 8) + lane7;
        ax[mt] = mrow & 63;
        aly[mt] = mrow >> 6;
    }
    const int brow = ((l >> 4) & 1) * 8 + lane7;
    const int bcb = (l >> 3) & 1;

#pragma unroll
    for (int tap = 0; tap < 9; tap++) {
        if (tap < 8) cp_wait<1>(); else cp_wait<0>();
        __syncthreads();

        const int dy = tap / 3 - 1;
        const int dx = tap % 3 - 1;
        uint32_t abase[2];
        int akey[2];
#pragma unroll
        for (int mt = 0; mt < 2; mt++) {
            int p = (aly[mt] + dy + 1) * 66 + ax[mt] + dx + 1;
            akey[mt] = p & 7;
            abase[mt] = sb + p * 128;
        }
        const uint32_t btap = sb + B1_OFF + (tap & 1) * 16384;
#pragma unroll
        for (int kb = 0; kb < 4; kb++) {
            uint32_t ah[2][4], al[2][4];
#pragma unroll
            for (int mt = 0; mt < 2; mt++) {
                int chunk = kb * 2 + hi16;
                uint32_t sw = (uint32_t)((chunk ^ akey[mt]) << 4);
                ldsm4(ah[mt], abase[mt] + sw);
                ldsm4(al[mt], abase[mt] + AL_OFF + sw);
            }
#pragma unroll
            for (int nbl = 0; nbl < 2; nbl++) {
                int nbp = wn * 2 + nbl;
                int n = nbp * 16 + brow;
                uint32_t baddr = btap + n * 128 +
                                 (uint32_t)((((kb * 2 + bcb) ^ (n & 7))) << 4);
                uint32_t bh[4], bl[4];
                ldsm4(bh, baddr);
                ldsm4(bl, baddr + 8192);
#pragma unroll
                for (int mt = 0; mt < 2; mt++) {
                    mma16816(d[mt][2 * nbl], ah[mt], bh);
                    mma16816(d[mt][2 * nbl], al[mt], bh);
                    mma16816(d[mt][2 * nbl], ah[mt], bl);
                    mma16816(d[mt][2 * nbl + 1], ah[mt], bh + 2);
                    mma16816(d[mt][2 * nbl + 1], al[mt], bh + 2);
                    mma16816(d[mt][2 * nbl + 1], ah[mt], bl + 2);
                }
            }
        }
        __syncthreads();
        if (tap + 2 <= 8) {
            const uint8_t* src = g_wtile + (tap + 2) * 16384;
            uint32_t dst = sb + B1_OFF + (tap & 1) * 16384;
#pragma unroll
            for (int i = 0; i < 4; i++) {
                int idx = tid + i * 256;
                cp16(dst + idx * 16, src + idx * 16);
            }
            cp_commit();
        }
    }

    // epilogue: bias+relu -> fp16 single pixel-major [b][pix][ci2]
    const int lr = l >> 2;
    const int lc2 = l & 3;
#pragma unroll
    for (int mt = 0; mt < 2; mt++) {
#pragma unroll
        for (int nbl = 0; nbl < 4; nbl++) {
            int nb = wn * 4 + nbl;
            float b0 = *(const float*)(smem + BIAS1_OFF + (nb * 8 + lc2 * 2) * 4);
            float b1 = *(const float*)(smem + BIAS1_OFF + (nb * 8 + lc2 * 2 + 1) * 4);
#pragma unroll
            for (int row = 0; row < 2; row++) {
                int m = wm * 32 + mt * 16 + lr + row * 8;
                float v0 = fmaxf(d[mt][nbl][row * 2 + 0] + b0, 0.f);
                float v1 = fmaxf(d[mt][nbl][row * 2 + 1] + b1, 0.f);
                long o = ((long)b * 4096 + y0 * 64 + m) * 32 + nb * 4 + lc2;
                g_x2[o] = pack_f16x2(v0, v1);
            }
        }
    }
}

// ---------------------------------------------------------------------------
// conv2: fp16 single-term; 128 threads, 4 warps, warp tile M=32 x N=16.
// smem 52.3KB -> 4 CTAs/SM. Sigmoid straight into d_out.
// ---------------------------------------------------------------------------
__global__ __launch_bounds__(128) void conv2_mma_kernel(
    const float* __restrict__ bias, float* __restrict__ attn)
{
    extern __shared__ char smem[];
    const uint32_t sb = smem_u32(smem);
    const int tid = threadIdx.x;
    const int w = tid >> 5;
    const int l = tid & 31;
    const int b = blockIdx.x >> 5;
    const int y0 = (blockIdx.x & 31) * 2;

    if (tid < 16) *(float*)(smem + C2_BIAS + tid * 4) = bias[tid];

    // stage all 9 B tiles (fp16 single, pre-swizzled): 1152 uint4
    {
        const uint4* wsrc = (const uint4*)g_wtile2;
        uint4* dst = (uint4*)(smem + C2_B);
#pragma unroll
        for (int i = 0; i < 9; i++) dst[tid + i * 128] = wsrc[tid + i * 128];
    }
    // stage fp16 halo (single buffer)
    {
        const uint4* x4 = (const uint4*)g_x2;
        for (int p = tid; p < AHALO_PIX; p += 128) {
            int r = p / 66, c = p - r * 66;
            int y = y0 - 1 + r;
            int x = c - 1;
            bool ok = ((unsigned)y < 64u) && ((unsigned)x < 64u);
            long pix8 = ((long)b * 4096 + y * 64 + x) * 8;
            char* dh = smem + p * 128;
            int key = p & 7;
#pragma unroll
            for (int q = 0; q < 8; q++) {
                uint4 v = make_uint4(0, 0, 0, 0);
                if (ok) v = x4[pix8 + q];
                *(uint4*)(dh + ((q ^ key) << 4)) = v;
            }
        }
    }
    __syncthreads();

    float d[2][2][4];
#pragma unroll
    for (int mt = 0; mt < 2; mt++)
#pragma unroll
        for (int nb = 0; nb < 2; nb++)
#pragma unroll
            for (int j = 0; j < 4; j++) d[mt][nb][j] = 0.f;

    const int lane7 = l & 7;
    const int hi16 = (l >> 4) & 1;
    int ax[2], aly[2];
#pragma unroll
    for (int mt = 0; mt < 2; mt++) {
        int mrow = w * 32 + mt * 16 + (l & 8) + lane7;
        ax[mt] = mrow & 63;
        aly[mt] = mrow >> 6;
    }
    const int brow = ((l >> 4) & 1) * 8 + lane7;
    const int bcb = (l >> 3) & 1;

#pragma unroll
    for (int tap = 0; tap < 9; tap++) {
        const int dy = tap / 3 - 1;
        const int dx = tap % 3 - 1;
        uint32_t abase[2];
        int akey[2];
#pragma unroll
        for (int mt = 0; mt < 2; mt++) {
            int p = (aly[mt] + dy + 1) * 66 + ax[mt] + dx + 1;
            akey[mt] = p & 7;
            abase[mt] = sb + p * 128;
        }
        const uint32_t btap = sb + C2_B + tap * 2048;
#pragma unroll
        for (int kb = 0; kb < 4; kb++) {
            uint32_t ah[2][4];
#pragma unroll
            for (int mt = 0; mt < 2; mt++) {
                int chunk = kb * 2 + hi16;
                ldsm4(ah[mt], abase[mt] + (uint32_t)((chunk ^ akey[mt]) << 4));
            }
            {
                int n = brow;
                uint32_t baddr = btap + n * 128 +
                                 (uint32_t)((((kb * 2 + bcb) ^ (n & 7))) << 4);
                uint32_t bh[4];
                ldsm4(bh, baddr);
#pragma unroll
                for (int mt = 0; mt < 2; mt++) {
                    mma16816h(d[mt][0], ah[mt], bh);
                    mma16816h(d[mt][1], ah[mt], bh + 2);
                }
            }
        }
    }

    // epilogue: bias + sigmoid -> attn NCHW fp32 (straight into d_out)
    const int lr = l >> 2;
    const int lc = (l & 3) * 2;
#pragma unroll
    for (int mt = 0; mt < 2; mt++) {
#pragma unroll
        for (int nb = 0; nb < 2; nb++) {
#pragma unroll
            for (int j = 0; j < 4; j++) {
                int n = nb * 8 + lc + (j & 1);
                int m = w * 32 + mt * 16 + lr + ((j >> 1) * 8);
                float v = d[mt][nb][j] + *(const float*)(smem + C2_BIAS + n * 4);
                v = 1.f / (1.f + __expf(-v));
                attn[((long)(b * 16 + n)) * 4096 + y0 * 64 + m] = v;
            }
        }
    }
}

// ---------------------------------------------------------------------------
// fuse: cs-GEMM on HMMA (state bf16 hi/lo x c3_w) + relu-reduction partials.
// ---------------------------------------------------------------------------
#define F_AH 0
#define F_AL 16384
#define F_B  32768               /* hi 8K, lo 8K */
#define F_CS 49152               /* 128 x 68 fp32 = 34816 */
#define F_ATT 83968              /* 16 x 128 fp32 = 8192 */
#define FUSE_SMEM 92160

__global__ __launch_bounds__(256) void fuse_kernel(
    const float* __restrict__ attn, const float* __restrict__ c3_b)
{
    extern __shared__ char smem[];
    const uint32_t sb = smem_u32(smem);
    float* cs_s = (float*)(smem + F_CS);
    float* attn_s = (float*)(smem + F_ATT);

    const int tid = threadIdx.x;
    const int w8 = tid >> 5;
    const int wm = w8 & 3;
    const int wn = w8 >> 2;
    const int l = tid & 31;
    const int b = blockIdx.x >> 5;
    const int chunk = blockIdx.x & 31;
    const int pbase = chunk * 128;

    {
        const uint8_t* srch = (const uint8_t*)g_xhi + ((long)b * 4096 + pbase) * 128;
        const uint8_t* srcl = (const uint8_t*)g_xlo + ((long)b * 4096 + pbase) * 128;
#pragma unroll
        for (int i = 0; i < 4; i++) {
            int idx = tid + i * 256;       // (pp, q)
            int pp = idx >> 3, q = idx & 7;
            uint32_t sw = (uint32_t)(pp * 128 + ((q ^ (pp & 7)) << 4));
            cp16(sb + F_AH + sw, srch + idx * 16);
            cp16(sb + F_AL + sw, srcl + idx * 16);
        }
#pragma unroll
        for (int i = 0; i < 4; i++) {
            int idx = tid + i * 256;
            cp16(sb + F_B + idx * 16, g_wtile3 + idx * 16);
        }
#pragma unroll
        for (int i = 0; i < 2; i++) {
            int idx = tid + i * 256;       // 16B unit: (e, pp/4)
            int e = idx >> 5, p4 = idx & 31;
            cp16(sb + F_ATT + idx * 16,
                 attn + ((long)b * 16 + e) * HW + pbase + p4 * 4);
        }
        cp_commit();
        cp_wait<0>();
        __syncthreads();
    }

    float d[2][4][4];
#pragma unroll
    for (int mt = 0; mt < 2; mt++)
#pragma unroll
        for (int nb = 0; nb < 4; nb++)
#pragma unroll
            for (int j = 0; j < 4; j++) d[mt][nb][j] = 0.f;

    const int lane7 = l & 7;
    const int hi16 = (l >> 4) & 1;
    const int brow = ((l >> 4) & 1) * 8 + lane7;
    const int bcb = (l >> 3) & 1;

#pragma unroll
    for (int kb = 0; kb < 4; kb++) {
        uint32_t ah[2][4], al[2][4];
#pragma unroll
        for (int mt = 0; mt < 2; mt++) {
            int pp = wm * 32 + mt * 16 + (l & 8) + lane7;
            int chunkq = kb * 2 + hi16;
            uint32_t sw = (uint32_t)(pp * 128 + ((chunkq ^ (pp & 7)) << 4));
            ldsm4(ah[mt], sb + F_AH + sw);
            ldsm4(al[mt], sb + F_AL + sw);
        }
#pragma unroll
        for (int nbl = 0; nbl < 2; nbl++) {
            int nbp = wn * 2 + nbl;
            int n = nbp * 16 + brow;
            uint32_t baddr = sb + F_B + n * 128 +
                             (uint32_t)((((kb * 2 + bcb) ^ (n & 7))) << 4);
            uint32_t bh[4], bl[4];
            ldsm4(bh, baddr);
            ldsm4(bl, baddr + 8192);
#pragma unroll
            for (int mt = 0; mt < 2; mt++) {
                mma16816(d[mt][2 * nbl], ah[mt], bh);
                mma16816(d[mt][2 * nbl], al[mt], bh);
                mma16816(d[mt][2 * nbl], ah[mt], bl);
                mma16816(d[mt][2 * nbl + 1], ah[mt], bh + 2);
                mma16816(d[mt][2 * nbl + 1], al[mt], bh + 2);
                mma16816(d[mt][2 * nbl + 1], ah[mt], bl + 2);
            }
        }
    }

    {
        const int lr = l >> 2;
        const int lc = (l & 3) * 2;
#pragma unroll
        for (int mt = 0; mt < 2; mt++) {
#pragma unroll
            for (int nbl = 0; nbl < 4; nbl++) {
                int nb = wn * 4 + nbl;
#pragma unroll
                for (int row = 0; row < 2; row++) {
                    int m = wm * 32 + mt * 16 + lr + row * 8;
                    int n = nb * 8 + lc;
                    float2 v = make_float2(d[mt][nbl][row * 2 + 0],
                                           d[mt][nbl][row * 2 + 1]);
                    *(float2*)(cs_s + m * 68 + n) = v;
                }
            }
        }
    }
    __syncthreads();

    {
        const int e = tid >> 4;
        const int oq = tid & 15;
        const float4 bias = ((const float4*)c3_b)[oq];
        float4 acc = make_float4(0.f, 0.f, 0.f, 0.f);
        const float* arow = attn_s + e * 128;
#pragma unroll 4
        for (int pp = 0; pp < 128; pp++) {
            float a = arow[pp];
            float4 cv = *(const float4*)(cs_s + pp * 68 + oq * 4);
            acc.x += fmaxf(fmaf(a, cv.x, bias.x), 0.f);
            acc.y += fmaxf(fmaf(a, cv.y, bias.y), 0.f);
            acc.z += fmaxf(fmaf(a, cv.z, bias.z), 0.f);
            acc.w += fmaxf(fmaf(a, cv.w, bias.w), 0.f);
        }
        float4* po = (float4*)(g_partials + ((long)(b * 32 + chunk)) * 1024 + e * 64 + oq * 4);
        *po = acc;
    }
}

__global__ __launch_bounds__(256) void reduce_kernel(
    const float* __restrict__ c3_b, float* __restrict__ out)
{
    int gid = blockIdx.x * 256 + threadIdx.x;
    int o = gid & 63;
    float sum = 260.f * fmaxf(c3_b[o], 0.f);
    int b = gid >> 10;
    int eo = gid & 1023;
    const float* p = g_partials + (long)b * 32 * 1024 + eo;
#pragma unroll
    for (int c = 0; c < 32; c++) sum += p[c * 1024];
    out[gid] = sum * (1.f / 4356.f);
}

// ---------------------------------------------------------------------------
extern "C" void kernel_launch(void* const* d_in, const int* in_sizes, int n_in,
                              void* d_out, int out_size)
{
    const float* state = (const float*)d_in[0];
    const float* pre_w = (const float*)d_in[1];
    const float* pre_b = (const float*)d_in[2];
    const float* attn_w = (const float*)d_in[3];
    const float* attn_b = (const float*)d_in[4];
    const float* c3_w = (const float*)d_in[5];
    const float* c3_b = (const float*)d_in[6];

    float* out = (float*)d_out;
    float* attn = out + Bn * Ec * Fc;

    cudaFuncSetAttribute(fuse_kernel, cudaFuncAttributeMaxDynamicSharedMemorySize,
                         FUSE_SMEM);
    cudaFuncSetAttribute(conv1_mma_kernel, cudaFuncAttributeMaxDynamicSharedMemorySize,
                         CONV1_SMEM);
    cudaFuncSetAttribute(conv2_mma_kernel, cudaFuncAttributeMaxDynamicSharedMemorySize,
                         CONV2_SMEM);

    // prep: all weights + state
    wprep_all_kernel<<<98, 256>>>(pre_w, attn_w, c3_w);
    xprep_kernel<<<Bn * 64, 256>>>(state);
    // conv1: bf16 3-term HMMA; emits x as fp16
    conv1_mma_kernel<<<Bn * 32, 256, CONV1_SMEM>>>(pre_b);
    // conv2: fp16 single-term HMMA, 4 CTAs/SM
    conv2_mma_kernel<<<Bn * 32, 128, CONV2_SMEM>>>(attn_b, attn);
    // fuse: cs-GEMM (bf16 3-term) + relu-reduction partials
    fuse_kernel<<<Bn * 32, 256, FUSE_SMEM>>>(attn, c3_b);
    // final reduce + pad term
    reduce_kernel<<<64, 256>>>(c3_b, out);
}

// round 12
// speedup vs baseline: 1.7910x; 1.4837x over previous
#include <cuda_runtime.h>
#include <cuda_bf16.h>
#include <cuda_fp16.h>
#include <cstdint>

// Problem constants
#define Bn 16
#define Fc 64
#define Ec 16
#define Hh 64
#define Ww 64
#define HW (Hh * Ww)

// Scratch (device globals: allocation-free rule)
__device__ float g_partials[Bn * 32 * 16 * 64];          // fuse partial sums
__device__ __align__(16) uint32_t g_x1[Bn * HW * 32];    // state fp16 [b][pix][ci2]
__device__ __align__(16) uint32_t g_x2[Bn * HW * 32];    // relu(conv1) fp16 [b][pix][ci2]
__device__ __align__(16) uint8_t  g_wt1[9 * 8192];       // conv1 W fp16 swizzled [tap][co][ci]
__device__ __align__(16) uint8_t  g_wt2[9 * 2048];       // conv2 W fp16 swizzled
__device__ __align__(16) uint8_t  g_wt3[8192];           // c3_w fp16 swizzled [o][f]

// ---------------------------------------------------------------------------
// mma.sync + ldmatrix + cp.async (baseline PTX, legal at compute_103)
// ---------------------------------------------------------------------------
__device__ __forceinline__ void mma16816h(float* d, const uint32_t* a, const uint32_t* b)
{
    asm volatile(
        "mma.sync.aligned.m16n8k16.row.col.f32.f16.f16.f32 "
        "{%0,%1,%2,%3}, {%4,%5,%6,%7}, {%8,%9}, {%0,%1,%2,%3};"
        : "+f"(d[0]), "+f"(d[1]), "+f"(d[2]), "+f"(d[3])
        : "r"(a[0]), "r"(a[1]), "r"(a[2]), "r"(a[3]), "r"(b[0]), "r"(b[1]));
}

__device__ __forceinline__ void ldsm4(uint32_t* r, uint32_t addr)
{
    asm volatile("ldmatrix.sync.aligned.m8n8.x4.shared.b16 {%0,%1,%2,%3}, [%4];"
                 : "=r"(r[0]), "=r"(r[1]), "=r"(r[2]), "=r"(r[3]) : "r"(addr));
}

__device__ __forceinline__ void cp16(uint32_t dst, const void* src)
{
    asm volatile("cp.async.cg.shared.global [%0], [%1], 16;" :: "r"(dst), "l"(src));
}
__device__ __forceinline__ void cp_commit()
{
    asm volatile("cp.async.commit_group;" ::: "memory");
}
template <int N>
__device__ __forceinline__ void cp_wait()
{
    asm volatile("cp.async.wait_group %0;" :: "n"(N) : "memory");
}

__device__ __forceinline__ uint32_t smem_u32(const void* p)
{
    uint32_t a;
    asm("{ .reg .u64 t; cvta.to.shared.u64 t, %1; cvt.u32.u64 %0, t; }" : "=r"(a) : "l"(p));
    return a;
}

__device__ __forceinline__ uint32_t pack_f16x2(float v0, float v1)
{
    __half2 h = __floats2half2_rn(v0, v1);
    return *(uint32_t*)&h;
}

// ---------------------------------------------------------------------------
// Weight prep (all fp16 single): conv1 / conv2 / c3_w  (swizzle q ^= row&7)
// blocks 0..71: conv1; 72..89: conv2; 90..97: c3_w
// ---------------------------------------------------------------------------
__global__ __launch_bounds__(256) void wprep_all_kernel(
    const float* __restrict__ w1, const float* __restrict__ w2,
    const float* __restrict__ w3)
{
    int bi = blockIdx.x;
    if (bi < 72) {
        int idx = bi * 256 + threadIdx.x;          // (tap, co64, ci-pair)
        int tap = idx >> 11;
        int rem = idx & 2047;
        int co = rem >> 5, ci2 = rem & 31;
        float v0 = w1[(co * 64 + 2 * ci2) * 9 + tap];
        float v1 = w1[(co * 64 + 2 * ci2 + 1) * 9 + tap];
        int q = ci2 >> 2, wd = ci2 & 3;
        int sw = ((q ^ (co & 7)) << 4) + wd * 4;
        *(uint32_t*)(g_wt1 + tap * 8192 + co * 128 + sw) = pack_f16x2(v0, v1);
    } else if (bi < 90) {
        int idx = (bi - 72) * 256 + threadIdx.x;   // (tap, co16, ci-pair)
        if (idx >= 9 * 512) return;
        int tap = idx >> 9;
        int rem = idx & 511;
        int co = rem >> 5, ci2 = rem & 31;
        float v0 = w2[(co * 64 + 2 * ci2) * 9 + tap];
        float v1 = w2[(co * 64 + 2 * ci2 + 1) * 9 + tap];
        int q = ci2 >> 2, wd = ci2 & 3;
        int sw = ((q ^ (co & 7)) << 4) + wd * 4;
        *(uint32_t*)(g_wt2 + tap * 2048 + co * 128 + sw) = pack_f16x2(v0, v1);
    } else {
        int idx = (bi - 90) * 256 + threadIdx.x;   // (o64, f-pair)
        if (idx >= 2048) return;
        int o = idx >> 5, f2 = idx & 31;
        float v0 = w3[o * 64 + 2 * f2];
        float v1 = w3[o * 64 + 2 * f2 + 1];
        int q = f2 >> 2, wd = f2 & 3;
        int sw = ((q ^ (o & 7)) << 4) + wd * 4;
        *(uint32_t*)(g_wt3 + o * 128 + sw) = pack_f16x2(v0, v1);
    }
}

// ---------------------------------------------------------------------------
// Prep: state NCHW fp32 -> [b][pix][ci] fp16 (pixel-major, 128B/pixel)
// ---------------------------------------------------------------------------
__global__ __launch_bounds__(256) void xprep_kernel(const float* __restrict__ state)
{
    __shared__ float s[64 * 65];
    int b = blockIdx.x >> 6, y = blockIdx.x & 63;
    int tid = threadIdx.x;
#pragma unroll
    for (int k = 0; k < 16; k++) {
        int idx = tid + k * 256;
        int ci = idx >> 6, x = idx & 63;
        s[ci * 65 + x] = state[((long)(b * 64 + ci) * 64 + y) * 64 + x];
    }
    __syncthreads();
#pragma unroll
    for (int k = 0; k < 8; k++) {
        int idx = tid + k * 256;
        int x = idx >> 5, j = idx & 31;
        float v0 = s[(2 * j) * 65 + x];
        float v1 = s[(2 * j + 1) * 65 + x];
        g_x1[((long)b * 4096 + y * 64 + x) * 32 + j] = pack_f16x2(v0, v1);
    }
}

// ---------------------------------------------------------------------------
// Conv smem layouts
// ---------------------------------------------------------------------------
#define AHALO_PIX 264            /* 4 * 66 */
// conv1 (fp16): halo 33792 + B 2x8192 + bias
#define B1_OFF 33792
#define BIAS1_OFF (B1_OFF + 16384)             /* 50176 */
#define CONV1_SMEM (BIAS1_OFF + 256)           /* 50432 */
// conv2 (fp16): halo 33792 + B 9*2048 + bias
#define C2_B 33792
#define C2_BIAS (C2_B + 18432)                 /* 52224 */
#define CONV2_SMEM (C2_BIAS + 64)              /* 52288 */

// fp16 single-buffer halo stage
template <int NT>
__device__ __forceinline__ void stage_halo1(
    char* smem, const uint4* x4, int b, int y0, int tid)
{
    for (int p = tid; p < AHALO_PIX; p += NT) {
        int r = p / 66, c = p - r * 66;
        int y = y0 - 1 + r;
        int x = c - 1;
        bool ok = ((unsigned)y < 64u) && ((unsigned)x < 64u);
        long pix8 = ((long)b * 4096 + y * 64 + x) * 8;
        char* dh = smem + p * 128;
        int key = p & 7;
#pragma unroll
        for (int q = 0; q < 8; q++) {
            uint4 v = make_uint4(0, 0, 0, 0);
            if (ok) v = x4[pix8 + q];
            *(uint4*)(dh + ((q ^ key) << 4)) = v;
        }
    }
}

// ---------------------------------------------------------------------------
// conv1: fp16 single; 256 threads, 8 warps (wm x wn), warp tile 32x32.
// B double-buffered via cp.async; 4 CTAs/SM. Epilogue relu -> fp16 x.
// ---------------------------------------------------------------------------
__global__ __launch_bounds__(256) void conv1_mma_kernel(const float* __restrict__ bias)
{
    extern __shared__ char smem[];
    const uint32_t sb = smem_u32(smem);
    const int tid = threadIdx.x;
    const int w8 = tid >> 5;
    const int wm = w8 & 3;
    const int wn = w8 >> 2;
    const int l = tid & 31;
    const int b = blockIdx.x >> 5;
    const int y0 = (blockIdx.x & 31) * 2;

    if (tid < 64) *(float*)(smem + BIAS1_OFF + tid * 4) = bias[tid];

    // prefetch B tap0 -> buf0, tap1 -> buf1 (512 uint4 each)
#pragma unroll
    for (int i = 0; i < 2; i++) {
        int idx = tid + i * 256;
        cp16(sb + B1_OFF + idx * 16, g_wt1 + idx * 16);
    }
    cp_commit();
#pragma unroll
    for (int i = 0; i < 2; i++) {
        int idx = tid + i * 256;
        cp16(sb + B1_OFF + 8192 + idx * 16, g_wt1 + 8192 + idx * 16);
    }
    cp_commit();

    stage_halo1<256>(smem, (const uint4*)g_x1, b, y0, tid);

    float d[2][4][4];
#pragma unroll
    for (int mt = 0; mt < 2; mt++)
#pragma unroll
        for (int nb = 0; nb < 4; nb++)
#pragma unroll
            for (int j = 0; j < 4; j++) d[mt][nb][j] = 0.f;

    const int lane7 = l & 7;
    const int hi16 = (l >> 4) & 1;
    int ax[2], aly[2];
#pragma unroll
    for (int mt = 0; mt < 2; mt++) {
        int mrow = wm * 32 + mt * 16 + (l & 8) + lane7;
        ax[mt] = mrow & 63;
        aly[mt] = mrow >> 6;
    }
    const int brow = ((l >> 4) & 1) * 8 + lane7;
    const int bcb = (l >> 3) & 1;

#pragma unroll
    for (int tap = 0; tap < 9; tap++) {
        if (tap < 8) cp_wait<1>(); else cp_wait<0>();
        __syncthreads();

        const int dy = tap / 3 - 1;
        const int dx = tap % 3 - 1;
        uint32_t abase[2];
        int akey[2];
#pragma unroll
        for (int mt = 0; mt < 2; mt++) {
            int p = (aly[mt] + dy + 1) * 66 + ax[mt] + dx + 1;
            akey[mt] = p & 7;
            abase[mt] = sb + p * 128;
        }
        const uint32_t btap = sb + B1_OFF + (tap & 1) * 8192;
#pragma unroll
        for (int kb = 0; kb < 4; kb++) {
            uint32_t ah[2][4];
#pragma unroll
            for (int mt = 0; mt < 2; mt++) {
                int chunk = kb * 2 + hi16;
                ldsm4(ah[mt], abase[mt] + (uint32_t)((chunk ^ akey[mt]) << 4));
            }
#pragma unroll
            for (int nbl = 0; nbl < 2; nbl++) {
                int nbp = wn * 2 + nbl;
                int n = nbp * 16 + brow;
                uint32_t baddr = btap + n * 128 +
                                 (uint32_t)((((kb * 2 + bcb) ^ (n & 7))) << 4);
                uint32_t bh[4];
                ldsm4(bh, baddr);
#pragma unroll
                for (int mt = 0; mt < 2; mt++) {
                    mma16816h(d[mt][2 * nbl], ah[mt], bh);
                    mma16816h(d[mt][2 * nbl + 1], ah[mt], bh + 2);
                }
            }
        }
        __syncthreads();
        if (tap + 2 <= 8) {
            const uint8_t* src = g_wt1 + (tap + 2) * 8192;
            uint32_t dst = sb + B1_OFF + (tap & 1) * 8192;
#pragma unroll
            for (int i = 0; i < 2; i++) {
                int idx = tid + i * 256;
                cp16(dst + idx * 16, src + idx * 16);
            }
            cp_commit();
        }
    }

    // epilogue: bias+relu -> fp16 pixel-major [b][pix][ci2]
    const int lr = l >> 2;
    const int lc2 = l & 3;
#pragma unroll
    for (int mt = 0; mt < 2; mt++) {
#pragma unroll
        for (int nbl = 0; nbl < 4; nbl++) {
            int nb = wn * 4 + nbl;
            float b0 = *(const float*)(smem + BIAS1_OFF + (nb * 8 + lc2 * 2) * 4);
            float b1 = *(const float*)(smem + BIAS1_OFF + (nb * 8 + lc2 * 2 + 1) * 4);
#pragma unroll
            for (int row = 0; row < 2; row++) {
                int m = wm * 32 + mt * 16 + lr + row * 8;
                float v0 = fmaxf(d[mt][nbl][row * 2 + 0] + b0, 0.f);
                float v1 = fmaxf(d[mt][nbl][row * 2 + 1] + b1, 0.f);
                long o = ((long)b * 4096 + y0 * 64 + m) * 32 + nb * 4 + lc2;
                g_x2[o] = pack_f16x2(v0, v1);
            }
        }
    }
}

// ---------------------------------------------------------------------------
// conv2: fp16 single; 128 threads, warp tile M=32 x N=16; 4 CTAs/SM.
// ---------------------------------------------------------------------------
__global__ __launch_bounds__(128) void conv2_mma_kernel(
    const float* __restrict__ bias, float* __restrict__ attn)
{
    extern __shared__ char smem[];
    const uint32_t sb = smem_u32(smem);
    const int tid = threadIdx.x;
    const int w = tid >> 5;
    const int l = tid & 31;
    const int b = blockIdx.x >> 5;
    const int y0 = (blockIdx.x & 31) * 2;

    if (tid < 16) *(float*)(smem + C2_BIAS + tid * 4) = bias[tid];

    {
        const uint4* wsrc = (const uint4*)g_wt2;
        uint4* dst = (uint4*)(smem + C2_B);
#pragma unroll
        for (int i = 0; i < 9; i++) dst[tid + i * 128] = wsrc[tid + i * 128];
    }
    stage_halo1<128>(smem, (const uint4*)g_x2, b, y0, tid);
    __syncthreads();

    float d[2][2][4];
#pragma unroll
    for (int mt = 0; mt < 2; mt++)
#pragma unroll
        for (int nb = 0; nb < 2; nb++)
#pragma unroll
            for (int j = 0; j < 4; j++) d[mt][nb][j] = 0.f;

    const int lane7 = l & 7;
    const int hi16 = (l >> 4) & 1;
    int ax[2], aly[2];
#pragma unroll
    for (int mt = 0; mt < 2; mt++) {
        int mrow = w * 32 + mt * 16 + (l & 8) + lane7;
        ax[mt] = mrow & 63;
        aly[mt] = mrow >> 6;
    }
    const int brow = ((l >> 4) & 1) * 8 + lane7;
    const int bcb = (l >> 3) & 1;

#pragma unroll
    for (int tap = 0; tap < 9; tap++) {
        const int dy = tap / 3 - 1;
        const int dx = tap % 3 - 1;
        uint32_t abase[2];
        int akey[2];
#pragma unroll
        for (int mt = 0; mt < 2; mt++) {
            int p = (aly[mt] + dy + 1) * 66 + ax[mt] + dx + 1;
            akey[mt] = p & 7;
            abase[mt] = sb + p * 128;
        }
        const uint32_t btap = sb + C2_B + tap * 2048;
#pragma unroll
        for (int kb = 0; kb < 4; kb++) {
            uint32_t ah[2][4];
#pragma unroll
            for (int mt = 0; mt < 2; mt++) {
                int chunk = kb * 2 + hi16;
                ldsm4(ah[mt], abase[mt] + (uint32_t)((chunk ^ akey[mt]) << 4));
            }
            {
                int n = brow;
                uint32_t baddr = btap + n * 128 +
                                 (uint32_t)((((kb * 2 + bcb) ^ (n & 7))) << 4);
                uint32_t bh[4];
                ldsm4(bh, baddr);
#pragma unroll
                for (int mt = 0; mt < 2; mt++) {
                    mma16816h(d[mt][0], ah[mt], bh);
                    mma16816h(d[mt][1], ah[mt], bh + 2);
                }
            }
        }
    }

    // epilogue: bias + sigmoid -> attn NCHW fp32 (straight into d_out)
    const int lr = l >> 2;
    const int lc = (l & 3) * 2;
#pragma unroll
    for (int mt = 0; mt < 2; mt++) {
#pragma unroll
        for (int nb = 0; nb < 2; nb++) {
#pragma unroll
            for (int j = 0; j < 4; j++) {
                int n = nb * 8 + lc + (j & 1);
                int m = w * 32 + mt * 16 + lr + ((j >> 1) * 8);
                float v = d[mt][nb][j] + *(const float*)(smem + C2_BIAS + n * 4);
                v = 1.f / (1.f + __expf(-v));
                attn[((long)(b * 16 + n)) * 4096 + y0 * 64 + m] = v;
            }
        }
    }
}

// ---------------------------------------------------------------------------
// fuse: cs-GEMM fp16 (state x c3_w) + relu-reduction partials.
// block = (b, 128-pixel chunk); 256 threads, warp tile 32x32.
// ---------------------------------------------------------------------------
#define F_A  0                   /* 16384 */
#define F_B  16384               /* 8192 */
#define F_CS 24576               /* 128 x 68 fp32 = 34816 */
#define F_ATT 59392              /* 16 x 128 fp32 = 8192 */
#define FUSE_SMEM 67584

__global__ __launch_bounds__(256) void fuse_kernel(
    const float* __restrict__ attn, const float* __restrict__ c3_b)
{
    extern __shared__ char smem[];
    const uint32_t sb = smem_u32(smem);
    float* cs_s = (float*)(smem + F_CS);
    float* attn_s = (float*)(smem + F_ATT);

    const int tid = threadIdx.x;
    const int w8 = tid >> 5;
    const int wm = w8 & 3;
    const int wn = w8 >> 2;
    const int l = tid & 31;
    const int b = blockIdx.x >> 5;
    const int chunk = blockIdx.x & 31;
    const int pbase = chunk * 128;

    // stage A (128 pixels of state fp16, swizzled), B (c3_w), attn
    {
        const uint8_t* srca = (const uint8_t*)g_x1 + ((long)b * 4096 + pbase) * 128;
#pragma unroll
        for (int i = 0; i < 4; i++) {
            int idx = tid + i * 256;       // (pp, q), 1024 units
            int pp = idx >> 3, q = idx & 7;
            uint32_t sw = (uint32_t)(pp * 128 + ((q ^ (pp & 7)) << 4));
            cp16(sb + F_A + sw, srca + idx * 16);
        }
#pragma unroll
        for (int i = 0; i < 2; i++) {
            int idx = tid + i * 256;       // 512 units
            cp16(sb + F_B + idx * 16, g_wt3 + idx * 16);
        }
#pragma unroll
        for (int i = 0; i < 2; i++) {
            int idx = tid + i * 256;       // (e, pp/4), 512 units
            int e = idx >> 5, p4 = idx & 31;
            cp16(sb + F_ATT + idx * 16,
                 attn + ((long)b * 16 + e) * HW + pbase + p4 * 4);
        }
        cp_commit();
        cp_wait<0>();
        __syncthreads();
    }

    // cs-GEMM: D[128 pix][64 o] fp16 single-term
    float d[2][4][4];
#pragma unroll
    for (int mt = 0; mt < 2; mt++)
#pragma unroll
        for (int nb = 0; nb < 4; nb++)
#pragma unroll
            for (int j = 0; j < 4; j++) d[mt][nb][j] = 0.f;

    const int lane7 = l & 7;
    const int hi16 = (l >> 4) & 1;
    const int brow = ((l >> 4) & 1) * 8 + lane7;
    const int bcb = (l >> 3) & 1;

#pragma unroll
    for (int kb = 0; kb < 4; kb++) {
        uint32_t ah[2][4];
#pragma unroll
        for (int mt = 0; mt < 2; mt++) {
            int pp = wm * 32 + mt * 16 + (l & 8) + lane7;
            int chunkq = kb * 2 + hi16;
            uint32_t sw = (uint32_t)(pp * 128 + ((chunkq ^ (pp & 7)) << 4));
            ldsm4(ah[mt], sb + F_A + sw);
        }
#pragma unroll
        for (int nbl = 0; nbl < 2; nbl++) {
            int nbp = wn * 2 + nbl;
            int n = nbp * 16 + brow;
            uint32_t baddr = sb + F_B + n * 128 +
                             (uint32_t)((((kb * 2 + bcb) ^ (n & 7))) << 4);
            uint32_t bh[4];
            ldsm4(bh, baddr);
#pragma unroll
            for (int mt = 0; mt < 2; mt++) {
                mma16816h(d[mt][2 * nbl], ah[mt], bh);
                mma16816h(d[mt][2 * nbl + 1], ah[mt], bh + 2);
            }
        }
    }

    // write cs fragments to smem [pp][o] pitch 68
    {
        const int lr = l >> 2;
        const int lc = (l & 3) * 2;
#pragma unroll
        for (int mt = 0; mt < 2; mt++) {
#pragma unroll
            for (int nbl = 0; nbl < 4; nbl++) {
                int nb = wn * 4 + nbl;
#pragma unroll
                for (int row = 0; row < 2; row++) {
                    int m = wm * 32 + mt * 16 + lr + row * 8;
                    int n = nb * 8 + lc;
                    float2 v = make_float2(d[mt][nbl][row * 2 + 0],
                                           d[mt][nbl][row * 2 + 1]);
                    *(float2*)(cs_s + m * 68 + n) = v;
                }
            }
        }
    }
    __syncthreads();

    // relu-reduction: thread (e, oq) sums 4 o's over 128 pixels
    {
        const int e = tid >> 4;
        const int oq = tid & 15;
        const float4 bias = ((const float4*)c3_b)[oq];
        float4 acc = make_float4(0.f, 0.f, 0.f, 0.f);
        const float* arow = attn_s + e * 128;
#pragma unroll 4
        for (int pp = 0; pp < 128; pp++) {
            float a = arow[pp];
            float4 cv = *(const float4*)(cs_s + pp * 68 + oq * 4);
            acc.x += fmaxf(fmaf(a, cv.x, bias.x), 0.f);
            acc.y += fmaxf(fmaf(a, cv.y, bias.y), 0.f);
            acc.z += fmaxf(fmaf(a, cv.z, bias.z), 0.f);
            acc.w += fmaxf(fmaf(a, cv.w, bias.w), 0.f);
        }
        float4* po = (float4*)(g_partials + ((long)(b * 32 + chunk)) * 1024 + e * 64 + oq * 4);
        *po = acc;
    }
}

__global__ __launch_bounds__(256) void reduce_kernel(
    const float* __restrict__ c3_b, float* __restrict__ out)
{
    int gid = blockIdx.x * 256 + threadIdx.x;
    int o = gid & 63;
    float sum = 260.f * fmaxf(c3_b[o], 0.f);
    int b = gid >> 10;
    int eo = gid & 1023;
    const float* p = g_partials + (long)b * 32 * 1024 + eo;
#pragma unroll
    for (int c = 0; c < 32; c++) sum += p[c * 1024];
    out[gid] = sum * (1.f / 4356.f);
}

// ---------------------------------------------------------------------------
extern "C" void kernel_launch(void* const* d_in, const int* in_sizes, int n_in,
                              void* d_out, int out_size)
{
    const float* state = (const float*)d_in[0];
    const float* pre_w = (const float*)d_in[1];
    const float* pre_b = (const float*)d_in[2];
    const float* attn_w = (const float*)d_in[3];
    const float* attn_b = (const float*)d_in[4];
    const float* c3_w = (const float*)d_in[5];
    const float* c3_b = (const float*)d_in[6];

    float* out = (float*)d_out;
    float* attn = out + Bn * Ec * Fc;

    cudaFuncSetAttribute(fuse_kernel, cudaFuncAttributeMaxDynamicSharedMemorySize,
                         FUSE_SMEM);
    cudaFuncSetAttribute(conv1_mma_kernel, cudaFuncAttributeMaxDynamicSharedMemorySize,
                         CONV1_SMEM);
    cudaFuncSetAttribute(conv2_mma_kernel, cudaFuncAttributeMaxDynamicSharedMemorySize,
                         CONV2_SMEM);

    // prep: all weights + state to fp16
    wprep_all_kernel<<<98, 256>>>(pre_w, attn_w, c3_w);
    xprep_kernel<<<Bn * 64, 256>>>(state);
    // conv1: fp16 single-term HMMA, B double-buffered, 4 CTAs/SM
    conv1_mma_kernel<<<Bn * 32, 256, CONV1_SMEM>>>(pre_b);
    // conv2: fp16 single-term HMMA, 4 CTAs/SM
    conv2_mma_kernel<<<Bn * 32, 128, CONV2_SMEM>>>(attn_b, attn);
    // fuse: cs-GEMM fp16 + relu-reduction partials
    fuse_kernel<<<Bn * 32, 256, FUSE_SMEM>>>(attn, c3_b);
    // final reduce + pad term
    reduce_kernel<<<64, 256>>>(c3_b, out);
}

// round 14
// speedup vs baseline: 1.8453x; 1.0303x over previous
#include <cuda_runtime.h>
#include <cuda_bf16.h>
#include <cuda_fp16.h>
#include <cstdint>

// Problem constants
#define Bn 16
#define Fc 64
#define Ec 16
#define Hh 64
#define Ww 64
#define HW (Hh * Ww)

// Scratch (device globals: allocation-free rule)
__device__ __align__(16) uint32_t g_x1[Bn * HW * 32];    // state fp16 [b][pix][ci2]
__device__ __align__(16) uint32_t g_x2[Bn * HW * 32];    // relu(conv1) fp16 [b][pix][ci2]
__device__ __align__(16) uint8_t  g_wt1[9 * 8192];       // conv1 W fp16 swizzled [tap][co][ci]
__device__ __align__(16) uint8_t  g_wt2[9 * 2048];       // conv2 W fp16 swizzled
__device__ __align__(16) uint8_t  g_wt3[8192];           // c3_w fp16 swizzled [o][f]

// ---------------------------------------------------------------------------
// mma.sync + ldmatrix + cp.async (baseline PTX, legal at compute_103)
// ---------------------------------------------------------------------------
__device__ __forceinline__ void mma16816h(float* d, const uint32_t* a, const uint32_t* b)
{
    asm volatile(
        "mma.sync.aligned.m16n8k16.row.col.f32.f16.f16.f32 "
        "{%0,%1,%2,%3}, {%4,%5,%6,%7}, {%8,%9}, {%0,%1,%2,%3};"
        : "+f"(d[0]), "+f"(d[1]), "+f"(d[2]), "+f"(d[3])
        : "r"(a[0]), "r"(a[1]), "r"(a[2]), "r"(a[3]), "r"(b[0]), "r"(b[1]));
}

__device__ __forceinline__ void ldsm4(uint32_t* r, uint32_t addr)
{
    asm volatile("ldmatrix.sync.aligned.m8n8.x4.shared.b16 {%0,%1,%2,%3}, [%4];"
                 : "=r"(r[0]), "=r"(r[1]), "=r"(r[2]), "=r"(r[3]) : "r"(addr));
}

__device__ __forceinline__ void cp16(uint32_t dst, const void* src)
{
    asm volatile("cp.async.cg.shared.global [%0], [%1], 16;" :: "r"(dst), "l"(src));
}
__device__ __forceinline__ void cp_commit()
{
    asm volatile("cp.async.commit_group;" ::: "memory");
}
template <int N>
__device__ __forceinline__ void cp_wait()
{
    asm volatile("cp.async.wait_group %0;" :: "n"(N) : "memory");
}

__device__ __forceinline__ uint32_t smem_u32(const void* p)
{
    uint32_t a;
    asm("{ .reg .u64 t; cvta.to.shared.u64 t, %1; cvt.u32.u64 %0, t; }" : "=r"(a) : "l"(p));
    return a;
}

__device__ __forceinline__ uint32_t pack_f16x2(float v0, float v1)
{
    __half2 h = __floats2half2_rn(v0, v1);
    return *(uint32_t*)&h;
}

// ---------------------------------------------------------------------------
// Weight prep (all fp16 single) + d_out pad-term init.
// blocks 0..71: conv1; 72..89: conv2; 90..97: c3_w; 98..161: out init
// ---------------------------------------------------------------------------
__global__ __launch_bounds__(256) void wprep_all_kernel(
    const float* __restrict__ w1, const float* __restrict__ w2,
    const float* __restrict__ w3, const float* __restrict__ c3_b,
    float* __restrict__ out)
{
    int bi = blockIdx.x;
    if (bi < 72) {
        int idx = bi * 256 + threadIdx.x;          // (tap, co64, ci-pair)
        int tap = idx >> 11;
        int rem = idx & 2047;
        int co = rem >> 5, ci2 = rem & 31;
        float v0 = w1[(co * 64 + 2 * ci2) * 9 + tap];
        float v1 = w1[(co * 64 + 2 * ci2 + 1) * 9 + tap];
        int q = ci2 >> 2, wd = ci2 & 3;
        int sw = ((q ^ (co & 7)) << 4) + wd * 4;
        *(uint32_t*)(g_wt1 + tap * 8192 + co * 128 + sw) = pack_f16x2(v0, v1);
    } else if (bi < 90) {
        int idx = (bi - 72) * 256 + threadIdx.x;   // (tap, co16, ci-pair)
        if (idx >= 9 * 512) return;
        int tap = idx >> 9;
        int rem = idx & 511;
        int co = rem >> 5, ci2 = rem & 31;
        float v0 = w2[(co * 64 + 2 * ci2) * 9 + tap];
        float v1 = w2[(co * 64 + 2 * ci2 + 1) * 9 + tap];
        int q = ci2 >> 2, wd = ci2 & 3;
        int sw = ((q ^ (co & 7)) << 4) + wd * 4;
        *(uint32_t*)(g_wt2 + tap * 2048 + co * 128 + sw) = pack_f16x2(v0, v1);
    } else if (bi < 98) {
        int idx = (bi - 90) * 256 + threadIdx.x;   // (o64, f-pair)
        if (idx >= 2048) return;
        int o = idx >> 5, f2 = idx & 31;
        float v0 = w3[o * 64 + 2 * f2];
        float v1 = w3[o * 64 + 2 * f2 + 1];
        int q = f2 >> 2, wd = f2 & 3;
        int sw = ((q ^ (o & 7)) << 4) + wd * 4;
        *(uint32_t*)(g_wt3 + o * 128 + sw) = pack_f16x2(v0, v1);
    } else {
        // out[b][e][o] init with pad term: 260*relu(c3_b[o]) / 4356
        int gid = (bi - 98) * 256 + threadIdx.x;   // 0..16383
        int o = gid & 63;
        out[gid] = 260.f * fmaxf(c3_b[o], 0.f) * (1.f / 4356.f);
    }
}

// ---------------------------------------------------------------------------
// Prep: state NCHW fp32 -> [b][pix][ci] fp16 (pixel-major, 128B/pixel)
// ---------------------------------------------------------------------------
__global__ __launch_bounds__(256) void xprep_kernel(const float* __restrict__ state)
{
    __shared__ float s[64 * 65];
    int b = blockIdx.x >> 6, y = blockIdx.x & 63;
    int tid = threadIdx.x;
#pragma unroll
    for (int k = 0; k < 16; k++) {
        int idx = tid + k * 256;
        int ci = idx >> 6, x = idx & 63;
        s[ci * 65 + x] = state[((long)(b * 64 + ci) * 64 + y) * 64 + x];
    }
    __syncthreads();
#pragma unroll
    for (int k = 0; k < 8; k++) {
        int idx = tid + k * 256;
        int x = idx >> 5, j = idx & 31;
        float v0 = s[(2 * j) * 65 + x];
        float v1 = s[(2 * j + 1) * 65 + x];
        g_x1[((long)b * 4096 + y * 64 + x) * 32 + j] = pack_f16x2(v0, v1);
    }
}

// ---------------------------------------------------------------------------
// Smem layouts
// ---------------------------------------------------------------------------
// conv1 (2-row strip): halo 4x66 px + B 2x8192 double buffer + bias
#define AHALO4 264
#define B1_OFF 33792
#define BIAS1_OFF (B1_OFF + 16384)             /* 50176 */
#define CONV1_SMEM (BIAS1_OFF + 256)           /* 50432 */
// conv2 (4-row strip): halo 6x66 px + B 9*2048 + bias
#define AHALO6 396
#define C2_B 50688
#define C2_BIAS (C2_B + 18432)                 /* 69120 */
#define CONV2_SMEM (C2_BIAS + 64)              /* 69184 */

// fp16 halo stage (ROWS+2 rows x 66 cols), NT threads
template <int NT, int NPIX>
__device__ __forceinline__ void stage_halo1(
    char* smem, const uint4* x4, int b, int y0, int tid)
{
    for (int p = tid; p < NPIX; p += NT) {
        int r = p / 66, c = p - r * 66;
        int y = y0 - 1 + r;
        int x = c - 1;
        bool ok = ((unsigned)y < 64u) && ((unsigned)x < 64u);
        long pix8 = ((long)b * 4096 + y * 64 + x) * 8;
        char* dh = smem + p * 128;
        int key = p & 7;
#pragma unroll
        for (int q = 0; q < 8; q++) {
            uint4 v = make_uint4(0, 0, 0, 0);
            if (ok) v = x4[pix8 + q];
            *(uint4*)(dh + ((q ^ key) << 4)) = v;
        }
    }
}

// ---------------------------------------------------------------------------
// conv1: fp16; 256 threads, 8 warps (wm x wn), warp tile 32x32, 2-row strip.
// B double-buffered via cp.async; 4 CTAs/SM. Epilogue relu -> fp16 x.
// ---------------------------------------------------------------------------
__global__ __launch_bounds__(256) void conv1_mma_kernel(const float* __restrict__ bias)
{
    extern __shared__ char smem[];
    const uint32_t sb = smem_u32(smem);
    const int tid = threadIdx.x;
    const int w8 = tid >> 5;
    const int wm = w8 & 3;
    const int wn = w8 >> 2;
    const int l = tid & 31;
    const int b = blockIdx.x >> 5;
    const int y0 = (blockIdx.x & 31) * 2;

    if (tid < 64) *(float*)(smem + BIAS1_OFF + tid * 4) = bias[tid];

#pragma unroll
    for (int i = 0; i < 2; i++) {
        int idx = tid + i * 256;
        cp16(sb + B1_OFF + idx * 16, g_wt1 + idx * 16);
    }
    cp_commit();
#pragma unroll
    for (int i = 0; i < 2; i++) {
        int idx = tid + i * 256;
        cp16(sb + B1_OFF + 8192 + idx * 16, g_wt1 + 8192 + idx * 16);
    }
    cp_commit();

    stage_halo1<256, AHALO4>(smem, (const uint4*)g_x1, b, y0, tid);

    float d[2][4][4];
#pragma unroll
    for (int mt = 0; mt < 2; mt++)
#pragma unroll
        for (int nb = 0; nb < 4; nb++)
#pragma unroll
            for (int j = 0; j < 4; j++) d[mt][nb][j] = 0.f;

    const int lane7 = l & 7;
    const int hi16 = (l >> 4) & 1;
    int ax[2], aly[2];
#pragma unroll
    for (int mt = 0; mt < 2; mt++) {
        int mrow = wm * 32 + mt * 16 + (l & 8) + lane7;
        ax[mt] = mrow & 63;
        aly[mt] = mrow >> 6;
    }
    const int brow = ((l >> 4) & 1) * 8 + lane7;
    const int bcb = (l >> 3) & 1;

#pragma unroll
    for (int tap = 0; tap < 9; tap++) {
        if (tap < 8) cp_wait<1>(); else cp_wait<0>();
        __syncthreads();

        const int dy = tap / 3 - 1;
        const int dx = tap % 3 - 1;
        uint32_t abase[2];
        int akey[2];
#pragma unroll
        for (int mt = 0; mt < 2; mt++) {
            int p = (aly[mt] + dy + 1) * 66 + ax[mt] + dx + 1;
            akey[mt] = p & 7;
            abase[mt] = sb + p * 128;
        }
        const uint32_t btap = sb + B1_OFF + (tap & 1) * 8192;
#pragma unroll
        for (int kb = 0; kb < 4; kb++) {
            uint32_t ah[2][4];
#pragma unroll
            for (int mt = 0; mt < 2; mt++) {
                int chunk = kb * 2 + hi16;
                ldsm4(ah[mt], abase[mt] + (uint32_t)((chunk ^ akey[mt]) << 4));
            }
#pragma unroll
            for (int nbl = 0; nbl < 2; nbl++) {
                int nbp = wn * 2 + nbl;
                int n = nbp * 16 + brow;
                uint32_t baddr = btap + n * 128 +
                                 (uint32_t)((((kb * 2 + bcb) ^ (n & 7))) << 4);
                uint32_t bh[4];
                ldsm4(bh, baddr);
#pragma unroll
                for (int mt = 0; mt < 2; mt++) {
                    mma16816h(d[mt][2 * nbl], ah[mt], bh);
                    mma16816h(d[mt][2 * nbl + 1], ah[mt], bh + 2);
                }
            }
        }
        __syncthreads();
        if (tap + 2 <= 8) {
            const uint8_t* src = g_wt1 + (tap + 2) * 8192;
            uint32_t dst = sb + B1_OFF + (tap & 1) * 8192;
#pragma unroll
            for (int i = 0; i < 2; i++) {
                int idx = tid + i * 256;
                cp16(dst + idx * 16, src + idx * 16);
            }
            cp_commit();
        }
    }

    // epilogue: bias+relu -> fp16 pixel-major [b][pix][ci2]
    const int lr = l >> 2;
    const int lc2 = l & 3;
#pragma unroll
    for (int mt = 0; mt < 2; mt++) {
#pragma unroll
        for (int nbl = 0; nbl < 4; nbl++) {
            int nb = wn * 4 + nbl;
            float b0 = *(const float*)(smem + BIAS1_OFF + (nb * 8 + lc2 * 2) * 4);
            float b1 = *(const float*)(smem + BIAS1_OFF + (nb * 8 + lc2 * 2 + 1) * 4);
#pragma unroll
            for (int row = 0; row < 2; row++) {
                int m = wm * 32 + mt * 16 + lr + row * 8;
                float v0 = fmaxf(d[mt][nbl][row * 2 + 0] + b0, 0.f);
                float v1 = fmaxf(d[mt][nbl][row * 2 + 1] + b1, 0.f);
                long o = ((long)b * 4096 + y0 * 64 + m) * 32 + nb * 4 + lc2;
                g_x2[o] = pack_f16x2(v0, v1);
            }
        }
    }
}

// ---------------------------------------------------------------------------
// conv2: fp16; 4-row strip (M=256), 256 threads, 8 warps, warp tile 32x16.
// smem 69.2KB -> 3 CTAs/SM; grid 256. Sigmoid straight into d_out.
// ---------------------------------------------------------------------------
__global__ __launch_bounds__(256) void conv2_mma_kernel(
    const float* __restrict__ bias, float* __restrict__ attn)
{
    extern __shared__ char smem[];
    const uint32_t sb = smem_u32(smem);
    const int tid = threadIdx.x;
    const int w8 = tid >> 5;
    const int l = tid & 31;
    const int b = blockIdx.x >> 4;
    const int y0 = (blockIdx.x & 15) * 4;

    if (tid < 16) *(float*)(smem + C2_BIAS + tid * 4) = bias[tid];

    // stage all 9 B tiles (1152 uint4)
    {
        const uint4* wsrc = (const uint4*)g_wt2;
        uint4* dst = (uint4*)(smem + C2_B);
#pragma unroll
        for (int i = 0; i < 5; i++) {
            int idx = tid + i * 256;
            if (idx < 1152) dst[idx] = wsrc[idx];
        }
    }
    stage_halo1<256, AHALO6>(smem, (const uint4*)g_x2, b, y0, tid);
    __syncthreads();

    float d[2][2][4];
#pragma unroll
    for (int mt = 0; mt < 2; mt++)
#pragma unroll
        for (int nb = 0; nb < 2; nb++)
#pragma unroll
            for (int j = 0; j < 4; j++) d[mt][nb][j] = 0.f;

    const int lane7 = l & 7;
    const int hi16 = (l >> 4) & 1;
    int ax[2], aly[2];
#pragma unroll
    for (int mt = 0; mt < 2; mt++) {
        int mrow = w8 * 32 + mt * 16 + (l & 8) + lane7;
        ax[mt] = mrow & 63;
        aly[mt] = mrow >> 6;            // 0..3
    }
    const int brow = ((l >> 4) & 1) * 8 + lane7;
    const int bcb = (l >> 3) & 1;

#pragma unroll
    for (int tap = 0; tap < 9; tap++) {
        const int dy = tap / 3 - 1;
        const int dx = tap % 3 - 1;
        uint32_t abase[2];
        int akey[2];
#pragma unroll
        for (int mt = 0; mt < 2; mt++) {
            int p = (aly[mt] + dy + 1) * 66 + ax[mt] + dx + 1;
            akey[mt] = p & 7;
            abase[mt] = sb + p * 128;
        }
        const uint32_t btap = sb + C2_B + tap * 2048;
#pragma unroll
        for (int kb = 0; kb < 4; kb++) {
            uint32_t ah[2][4];
#pragma unroll
            for (int mt = 0; mt < 2; mt++) {
                int chunk = kb * 2 + hi16;
                ldsm4(ah[mt], abase[mt] + (uint32_t)((chunk ^ akey[mt]) << 4));
            }
            {
                int n = brow;
                uint32_t baddr = btap + n * 128 +
                                 (uint32_t)((((kb * 2 + bcb) ^ (n & 7))) << 4);
                uint32_t bh[4];
                ldsm4(bh, baddr);
#pragma unroll
                for (int mt = 0; mt < 2; mt++) {
                    mma16816h(d[mt][0], ah[mt], bh);
                    mma16816h(d[mt][1], ah[mt], bh + 2);
                }
            }
        }
    }

    // epilogue: bias + sigmoid -> attn NCHW fp32 (straight into d_out)
    const int lr = l >> 2;
    const int lc = (l & 3) * 2;
#pragma unroll
    for (int mt = 0; mt < 2; mt++) {
#pragma unroll
        for (int nb = 0; nb < 2; nb++) {
#pragma unroll
            for (int j = 0; j < 4; j++) {
                int n = nb * 8 + lc + (j & 1);
                int m = w8 * 32 + mt * 16 + lr + ((j >> 1) * 8);
                float v = d[mt][nb][j] + *(const float*)(smem + C2_BIAS + n * 4);
                v = 1.f / (1.f + __expf(-v));
                attn[((long)(b * 16 + n)) * 4096 + y0 * 64 + m] = v;
            }
        }
    }
}

// ---------------------------------------------------------------------------
// fuse: cs-GEMM fp16 (state x c3_w) + relu-reduction, atomicAdd into d_out.
// block = (b, 128-pixel chunk); 256 threads, warp tile 32x32.
// ---------------------------------------------------------------------------
#define F_A  0                   /* 16384 */
#define F_B  16384               /* 8192 */
#define F_CS 24576               /* 128 x 68 fp32 = 34816 */
#define F_ATT 59392              /* 16 x 128 fp32 = 8192 */
#define FUSE_SMEM 67584

__global__ __launch_bounds__(256) void fuse_kernel(
    const float* __restrict__ attn, const float* __restrict__ c3_b,
    float* __restrict__ out)
{
    extern __shared__ char smem[];
    const uint32_t sb = smem_u32(smem);
    float* cs_s = (float*)(smem + F_CS);
    float* attn_s = (float*)(smem + F_ATT);

    const int tid = threadIdx.x;
    const int w8 = tid >> 5;
    const int wm = w8 & 3;
    const int wn = w8 >> 2;
    const int l = tid & 31;
    const int b = blockIdx.x >> 5;
    const int chunk = blockIdx.x & 31;
    const int pbase = chunk * 128;

    // stage A (128 pixels of state fp16, swizzled), B (c3_w), attn
    {
        const uint8_t* srca = (const uint8_t*)g_x1 + ((long)b * 4096 + pbase) * 128;
#pragma unroll
        for (int i = 0; i < 4; i++) {
            int idx = tid + i * 256;       // (pp, q), 1024 units
            int pp = idx >> 3, q = idx & 7;
            uint32_t sw = (uint32_t)(pp * 128 + ((q ^ (pp & 7)) << 4));
            cp16(sb + F_A + sw, srca + idx * 16);
        }
#pragma unroll
        for (int i = 0; i < 2; i++) {
            int idx = tid + i * 256;       // 512 units
            cp16(sb + F_B + idx * 16, g_wt3 + idx * 16);
        }
#pragma unroll
        for (int i = 0; i < 2; i++) {
            int idx = tid + i * 256;       // (e, pp/4), 512 units
            int e = idx >> 5, p4 = idx & 31;
            cp16(sb + F_ATT + idx * 16,
                 attn + ((long)b * 16 + e) * HW + pbase + p4 * 4);
        }
        cp_commit();
        cp_wait<0>();
        __syncthreads();
    }

    // cs-GEMM: D[128 pix][64 o] fp16 single-term
    float d[2][4][4];
#pragma unroll
    for (int mt = 0; mt < 2; mt++)
#pragma unroll
        for (int nb = 0; nb < 4; nb++)
#pragma unroll
            for (int j = 0; j < 4; j++) d[mt][nb][j] = 0.f;

    const int lane7 = l & 7;
    const int hi16 = (l >> 4) & 1;
    const int brow = ((l >> 4) & 1) * 8 + lane7;
    const int bcb = (l >> 3) & 1;

#pragma unroll
    for (int kb = 0; kb < 4; kb++) {
        uint32_t ah[2][4];
#pragma unroll
        for (int mt = 0; mt < 2; mt++) {
            int pp = wm * 32 + mt * 16 + (l & 8) + lane7;
            int chunkq = kb * 2 + hi16;
            uint32_t sw = (uint32_t)(pp * 128 + ((chunkq ^ (pp & 7)) << 4));
            ldsm4(ah[mt], sb + F_A + sw);
        }
#pragma unroll
        for (int nbl = 0; nbl < 2; nbl++) {
            int nbp = wn * 2 + nbl;
            int n = nbp * 16 + brow;
            uint32_t baddr = sb + F_B + n * 128 +
                             (uint32_t)((((kb * 2 + bcb) ^ (n & 7))) << 4);
            uint32_t bh[4];
            ldsm4(bh, baddr);
#pragma unroll
            for (int mt = 0; mt < 2; mt++) {
                mma16816h(d[mt][2 * nbl], ah[mt], bh);
                mma16816h(d[mt][2 * nbl + 1], ah[mt], bh + 2);
            }
        }
    }

    // write cs fragments to smem [pp][o] pitch 68
    {
        const int lr = l >> 2;
        const int lc = (l & 3) * 2;
#pragma unroll
        for (int mt = 0; mt < 2; mt++) {
#pragma unroll
            for (int nbl = 0; nbl < 4; nbl++) {
                int nb = wn * 4 + nbl;
#pragma unroll
                for (int row = 0; row < 2; row++) {
                    int m = wm * 32 + mt * 16 + lr + row * 8;
                    int n = nb * 8 + lc;
                    float2 v = make_float2(d[mt][nbl][row * 2 + 0],
                                           d[mt][nbl][row * 2 + 1]);
                    *(float2*)(cs_s + m * 68 + n) = v;
                }
            }
        }
    }
    __syncthreads();

    // relu-reduction: thread (e, oq) sums 4 o's over 128 pixels, atomicAdd out
    {
        const int e = tid >> 4;
        const int oq = tid & 15;
        const float4 bias = ((const float4*)c3_b)[oq];
        float4 acc = make_float4(0.f, 0.f, 0.f, 0.f);
        const float* arow = attn_s + e * 128;
#pragma unroll 4
        for (int pp = 0; pp < 128; pp++) {
            float a = arow[pp];
            float4 cv = *(const float4*)(cs_s + pp * 68 + oq * 4);
            acc.x += fmaxf(fmaf(a, cv.x, bias.x), 0.f);
            acc.y += fmaxf(fmaf(a, cv.y, bias.y), 0.f);
            acc.z += fmaxf(fmaf(a, cv.z, bias.z), 0.f);
            acc.w += fmaxf(fmaf(a, cv.w, bias.w), 0.f);
        }
        float* po = out + (long)b * 1024 + e * 64 + oq * 4;
        const float s = 1.f / 4356.f;
        atomicAdd(po + 0, acc.x * s);
        atomicAdd(po + 1, acc.y * s);
        atomicAdd(po + 2, acc.z * s);
        atomicAdd(po + 3, acc.w * s);
    }
}

// ---------------------------------------------------------------------------
extern "C" void kernel_launch(void* const* d_in, const int* in_sizes, int n_in,
                              void* d_out, int out_size)
{
    const float* state = (const float*)d_in[0];
    const float* pre_w = (const float*)d_in[1];
    const float* pre_b = (const float*)d_in[2];
    const float* attn_w = (const float*)d_in[3];
    const float* attn_b = (const float*)d_in[4];
    const float* c3_w = (const float*)d_in[5];
    const float* c3_b = (const float*)d_in[6];

    float* out = (float*)d_out;
    float* attn = out + Bn * Ec * Fc;

    cudaFuncSetAttribute(fuse_kernel, cudaFuncAttributeMaxDynamicSharedMemorySize,
                         FUSE_SMEM);
    cudaFuncSetAttribute(conv1_mma_kernel, cudaFuncAttributeMaxDynamicSharedMemorySize,
                         CONV1_SMEM);
    cudaFuncSetAttribute(conv2_mma_kernel, cudaFuncAttributeMaxDynamicSharedMemorySize,
                         CONV2_SMEM);

    // prep: weights + out pad-term init + state fp16
    wprep_all_kernel<<<162, 256>>>(pre_w, attn_w, c3_w, c3_b, out);
    xprep_kernel<<<Bn * 64, 256>>>(state);
    // conv1: fp16 HMMA, 2-row strips, B double-buffered, 4 CTAs/SM
    conv1_mma_kernel<<<Bn * 32, 256, CONV1_SMEM>>>(pre_b);
    // conv2: fp16 HMMA, 4-row strips, 3 CTAs/SM
    conv2_mma_kernel<<<Bn * 16, 256, CONV2_SMEM>>>(attn_b, attn);
    // fuse: cs-GEMM fp16 + relu-reduction, atomicAdd into out
    fuse_kernel<<<Bn * 32, 256, FUSE_SMEM>>>(attn, c3_b, out);
}

// round 15
// speedup vs baseline: 1.9214x; 1.0413x over previous
#include <cuda_runtime.h>
#include <cuda_bf16.h>
#include <cuda_fp16.h>
#include <cstdint>

// Problem constants
#define Bn 16
#define Fc 64
#define Ec 16
#define Hh 64
#define Ww 64
#define HW (Hh * Ww)

// Scratch (device globals: allocation-free rule)
__device__ __align__(16) uint32_t g_x1[Bn * HW * 32];    // state fp16 [b][pix][ci2]
__device__ __align__(16) uint32_t g_x2[Bn * HW * 32];    // relu(conv1) fp16 [b][pix][ci2]
__device__ __align__(16) uint8_t  g_wt1[9 * 8192];       // conv1 W fp16 swizzled [tap][co][ci]
__device__ __align__(16) uint8_t  g_wt2[9 * 2048];       // conv2 W fp16 swizzled
__device__ __align__(16) uint8_t  g_wt3[8192];           // c3_w fp16 swizzled [o][f]

// ---------------------------------------------------------------------------
// mma.sync + ldmatrix + cp.async (baseline PTX, legal at compute_103)
// ---------------------------------------------------------------------------
__device__ __forceinline__ void mma16816h(float* d, const uint32_t* a, const uint32_t* b)
{
    asm volatile(
        "mma.sync.aligned.m16n8k16.row.col.f32.f16.f16.f32 "
        "{%0,%1,%2,%3}, {%4,%5,%6,%7}, {%8,%9}, {%0,%1,%2,%3};"
        : "+f"(d[0]), "+f"(d[1]), "+f"(d[2]), "+f"(d[3])
        : "r"(a[0]), "r"(a[1]), "r"(a[2]), "r"(a[3]), "r"(b[0]), "r"(b[1]));
}

__device__ __forceinline__ void ldsm4(uint32_t* r, uint32_t addr)
{
    asm volatile("ldmatrix.sync.aligned.m8n8.x4.shared.b16 {%0,%1,%2,%3}, [%4];"
                 : "=r"(r[0]), "=r"(r[1]), "=r"(r[2]), "=r"(r[3]) : "r"(addr));
}

__device__ __forceinline__ void cp16(uint32_t dst, const void* src)
{
    asm volatile("cp.async.cg.shared.global [%0], [%1], 16;" :: "r"(dst), "l"(src));
}
// cp.async with zero-fill when sz == 0 (CUTLASS zfill idiom)
__device__ __forceinline__ void cp16z(uint32_t dst, const void* src, int sz)
{
    asm volatile("cp.async.cg.shared.global [%0], [%1], 16, %2;"
                 :: "r"(dst), "l"(src), "r"(sz));
}
__device__ __forceinline__ void cp_commit()
{
    asm volatile("cp.async.commit_group;" ::: "memory");
}
template <int N>
__device__ __forceinline__ void cp_wait()
{
    asm volatile("cp.async.wait_group %0;" :: "n"(N) : "memory");
}

__device__ __forceinline__ uint32_t smem_u32(const void* p)
{
    uint32_t a;
    asm("{ .reg .u64 t; cvta.to.shared.u64 t, %1; cvt.u32.u64 %0, t; }" : "=r"(a) : "l"(p));
    return a;
}

__device__ __forceinline__ uint32_t pack_f16x2(float v0, float v1)
{
    __half2 h = __floats2half2_rn(v0, v1);
    return *(uint32_t*)&h;
}

// ---------------------------------------------------------------------------
// Weight prep (all fp16 single) + d_out pad-term init.
// blocks 0..71: conv1; 72..89: conv2; 90..97: c3_w; 98..161: out init
// ---------------------------------------------------------------------------
__global__ __launch_bounds__(256) void wprep_all_kernel(
    const float* __restrict__ w1, const float* __restrict__ w2,
    const float* __restrict__ w3, const float* __restrict__ c3_b,
    float* __restrict__ out)
{
    int bi = blockIdx.x;
    if (bi < 72) {
        int idx = bi * 256 + threadIdx.x;          // (tap, co64, ci-pair)
        int tap = idx >> 11;
        int rem = idx & 2047;
        int co = rem >> 5, ci2 = rem & 31;
        float v0 = w1[(co * 64 + 2 * ci2) * 9 + tap];
        float v1 = w1[(co * 64 + 2 * ci2 + 1) * 9 + tap];
        int q = ci2 >> 2, wd = ci2 & 3;
        int sw = ((q ^ (co & 7)) << 4) + wd * 4;
        *(uint32_t*)(g_wt1 + tap * 8192 + co * 128 + sw) = pack_f16x2(v0, v1);
    } else if (bi < 90) {
        int idx = (bi - 72) * 256 + threadIdx.x;   // (tap, co16, ci-pair)
        if (idx >= 9 * 512) return;
        int tap = idx >> 9;
        int rem = idx & 511;
        int co = rem >> 5, ci2 = rem & 31;
        float v0 = w2[(co * 64 + 2 * ci2) * 9 + tap];
        float v1 = w2[(co * 64 + 2 * ci2 + 1) * 9 + tap];
        int q = ci2 >> 2, wd = ci2 & 3;
        int sw = ((q ^ (co & 7)) << 4) + wd * 4;
        *(uint32_t*)(g_wt2 + tap * 2048 + co * 128 + sw) = pack_f16x2(v0, v1);
    } else if (bi < 98) {
        int idx = (bi - 90) * 256 + threadIdx.x;   // (o64, f-pair)
        if (idx >= 2048) return;
        int o = idx >> 5, f2 = idx & 31;
        float v0 = w3[o * 64 + 2 * f2];
        float v1 = w3[o * 64 + 2 * f2 + 1];
        int q = f2 >> 2, wd = f2 & 3;
        int sw = ((q ^ (o & 7)) << 4) + wd * 4;
        *(uint32_t*)(g_wt3 + o * 128 + sw) = pack_f16x2(v0, v1);
    } else {
        // out[b][e][o] init with pad term: 260*relu(c3_b[o]) / 4356
        int gid = (bi - 98) * 256 + threadIdx.x;   // 0..16383
        int o = gid & 63;
        out[gid] = 260.f * fmaxf(c3_b[o], 0.f) * (1.f / 4356.f);
    }
}

// ---------------------------------------------------------------------------
// Prep: state NCHW fp32 -> [b][pix][ci] fp16 (pixel-major, 128B/pixel)
// ---------------------------------------------------------------------------
__global__ __launch_bounds__(256) void xprep_kernel(const float* __restrict__ state)
{
    __shared__ float s[64 * 65];
    int b = blockIdx.x >> 6, y = blockIdx.x & 63;
    int tid = threadIdx.x;
#pragma unroll
    for (int k = 0; k < 16; k++) {
        int idx = tid + k * 256;
        int ci = idx >> 6, x = idx & 63;
        s[ci * 65 + x] = state[((long)(b * 64 + ci) * 64 + y) * 64 + x];
    }
    __syncthreads();
#pragma unroll
    for (int k = 0; k < 8; k++) {
        int idx = tid + k * 256;
        int x = idx >> 5, j = idx & 31;
        float v0 = s[(2 * j) * 65 + x];
        float v1 = s[(2 * j + 1) * 65 + x];
        g_x1[((long)b * 4096 + y * 64 + x) * 32 + j] = pack_f16x2(v0, v1);
    }
}

// ---------------------------------------------------------------------------
// Smem layouts
// ---------------------------------------------------------------------------
// conv1 (2-row strip): halo 4x66 px + B 2x8192 double buffer + bias
#define AHALO4 264
#define B1_OFF 33792
#define BIAS1_OFF (B1_OFF + 16384)             /* 50176 */
#define CONV1_SMEM (BIAS1_OFF + 256)           /* 50432 */
// conv2 (4-row strip): halo 6x66 px + B 9*2048 + bias
#define AHALO6 396
#define C2_B 50688
#define C2_BIAS (C2_B + 18432)                 /* 69120 */
#define CONV2_SMEM (C2_BIAS + 64)              /* 69184 */

// fp16 halo stage via cp.async + zfill (ROWS+2 rows x 66 cols), NT threads.
// Issues cp.async only; caller commits/waits.
template <int NT, int NPIX>
__device__ __forceinline__ void stage_halo_async(
    uint32_t sb_halo, const uint8_t* x, int b, int y0, int tid)
{
    for (int p = tid; p < NPIX; p += NT) {
        int r = p / 66, c = p - r * 66;
        int y = y0 - 1 + r;
        int xx = c - 1;
        bool ok = ((unsigned)y < 64u) && ((unsigned)xx < 64u);
        const uint8_t* src = ok ? x + ((long)b * 4096 + y * 64 + xx) * 128 : x;
        int sz = ok ? 16 : 0;
        uint32_t dst = sb_halo + p * 128;
        int key = p & 7;
#pragma unroll
        for (int q = 0; q < 8; q++)
            cp16z(dst + ((q ^ key) << 4), src + q * 16, sz);
    }
}

// ---------------------------------------------------------------------------
// conv1: fp16; 256 threads, 8 warps (wm x wn), warp tile 32x32, 2-row strip.
// Halo + B tap0 in cp.async group0; B double-buffered; 4 CTAs/SM.
// ---------------------------------------------------------------------------
__global__ __launch_bounds__(256) void conv1_mma_kernel(const float* __restrict__ bias)
{
    extern __shared__ char smem[];
    const uint32_t sb = smem_u32(smem);
    const int tid = threadIdx.x;
    const int w8 = tid >> 5;
    const int wm = w8 & 3;
    const int wn = w8 >> 2;
    const int l = tid & 31;
    const int b = blockIdx.x >> 5;
    const int y0 = (blockIdx.x & 31) * 2;

    if (tid < 64) *(float*)(smem + BIAS1_OFF + tid * 4) = bias[tid];

    // G0: B tap0 + full halo
#pragma unroll
    for (int i = 0; i < 2; i++) {
        int idx = tid + i * 256;
        cp16(sb + B1_OFF + idx * 16, g_wt1 + idx * 16);
    }
    stage_halo_async<256, AHALO4>(sb, (const uint8_t*)g_x1, b, y0, tid);
    cp_commit();
    // G1: B tap1
#pragma unroll
    for (int i = 0; i < 2; i++) {
        int idx = tid + i * 256;
        cp16(sb + B1_OFF + 8192 + idx * 16, g_wt1 + 8192 + idx * 16);
    }
    cp_commit();

    float d[2][4][4];
#pragma unroll
    for (int mt = 0; mt < 2; mt++)
#pragma unroll
        for (int nb = 0; nb < 4; nb++)
#pragma unroll
            for (int j = 0; j < 4; j++) d[mt][nb][j] = 0.f;

    const int lane7 = l & 7;
    const int hi16 = (l >> 4) & 1;
    int ax[2], aly[2];
#pragma unroll
    for (int mt = 0; mt < 2; mt++) {
        int mrow = wm * 32 + mt * 16 + (l & 8) + lane7;
        ax[mt] = mrow & 63;
        aly[mt] = mrow >> 6;
    }
    const int brow = ((l >> 4) & 1) * 8 + lane7;
    const int bcb = (l >> 3) & 1;

#pragma unroll
    for (int tap = 0; tap < 9; tap++) {
        if (tap < 8) cp_wait<1>(); else cp_wait<0>();
        __syncthreads();

        const int dy = tap / 3 - 1;
        const int dx = tap % 3 - 1;
        uint32_t abase[2];
        int akey[2];
#pragma unroll
        for (int mt = 0; mt < 2; mt++) {
            int p = (aly[mt] + dy + 1) * 66 + ax[mt] + dx + 1;
            akey[mt] = p & 7;
            abase[mt] = sb + p * 128;
        }
        const uint32_t btap = sb + B1_OFF + (tap & 1) * 8192;
#pragma unroll
        for (int kb = 0; kb < 4; kb++) {
            uint32_t ah[2][4];
#pragma unroll
            for (int mt = 0; mt < 2; mt++) {
                int chunk = kb * 2 + hi16;
                ldsm4(ah[mt], abase[mt] + (uint32_t)((chunk ^ akey[mt]) << 4));
            }
#pragma unroll
            for (int nbl = 0; nbl < 2; nbl++) {
                int nbp = wn * 2 + nbl;
                int n = nbp * 16 + brow;
                uint32_t baddr = btap + n * 128 +
                                 (uint32_t)((((kb * 2 + bcb) ^ (n & 7))) << 4);
                uint32_t bh[4];
                ldsm4(bh, baddr);
#pragma unroll
                for (int mt = 0; mt < 2; mt++) {
                    mma16816h(d[mt][2 * nbl], ah[mt], bh);
                    mma16816h(d[mt][2 * nbl + 1], ah[mt], bh + 2);
                }
            }
        }
        __syncthreads();
        if (tap + 2 <= 8) {
            const uint8_t* src = g_wt1 + (tap + 2) * 8192;
            uint32_t dst = sb + B1_OFF + (tap & 1) * 8192;
#pragma unroll
            for (int i = 0; i < 2; i++) {
                int idx = tid + i * 256;
                cp16(dst + idx * 16, src + idx * 16);
            }
            cp_commit();
        }
    }

    // epilogue: bias+relu -> fp16 pixel-major [b][pix][ci2]
    const int lr = l >> 2;
    const int lc2 = l & 3;
#pragma unroll
    for (int mt = 0; mt < 2; mt++) {
#pragma unroll
        for (int nbl = 0; nbl < 4; nbl++) {
            int nb = wn * 4 + nbl;
            float b0 = *(const float*)(smem + BIAS1_OFF + (nb * 8 + lc2 * 2) * 4);
            float b1 = *(const float*)(smem + BIAS1_OFF + (nb * 8 + lc2 * 2 + 1) * 4);
#pragma unroll
            for (int row = 0; row < 2; row++) {
                int m = wm * 32 + mt * 16 + lr + row * 8;
                float v0 = fmaxf(d[mt][nbl][row * 2 + 0] + b0, 0.f);
                float v1 = fmaxf(d[mt][nbl][row * 2 + 1] + b1, 0.f);
                long o = ((long)b * 4096 + y0 * 64 + m) * 32 + nb * 4 + lc2;
                g_x2[o] = pack_f16x2(v0, v1);
            }
        }
    }
}

// ---------------------------------------------------------------------------
// conv2: fp16; 4-row strip (M=256), 256 threads, warp tile 32x16; 3 CTAs/SM.
// All staging via cp.async (B + halo, one group). Sigmoid into d_out.
// ---------------------------------------------------------------------------
__global__ __launch_bounds__(256) void conv2_mma_kernel(
    const float* __restrict__ bias, float* __restrict__ attn)
{
    extern __shared__ char smem[];
    const uint32_t sb = smem_u32(smem);
    const int tid = threadIdx.x;
    const int w8 = tid >> 5;
    const int l = tid & 31;
    const int b = blockIdx.x >> 4;
    const int y0 = (blockIdx.x & 15) * 4;

    if (tid < 16) *(float*)(smem + C2_BIAS + tid * 4) = bias[tid];

    // stage all 9 B tiles (1152 uint4) + halo, async, one group
#pragma unroll
    for (int i = 0; i < 5; i++) {
        int idx = tid + i * 256;
        if (idx < 1152) cp16(sb + C2_B + idx * 16, g_wt2 + idx * 16);
    }
    stage_halo_async<256, AHALO6>(sb, (const uint8_t*)g_x2, b, y0, tid);
    cp_commit();
    cp_wait<0>();
    __syncthreads();

    float d[2][2][4];
#pragma unroll
    for (int mt = 0; mt < 2; mt++)
#pragma unroll
        for (int nb = 0; nb < 2; nb++)
#pragma unroll
            for (int j = 0; j < 4; j++) d[mt][nb][j] = 0.f;

    const int lane7 = l & 7;
    const int hi16 = (l >> 4) & 1;
    int ax[2], aly[2];
#pragma unroll
    for (int mt = 0; mt < 2; mt++) {
        int mrow = w8 * 32 + mt * 16 + (l & 8) + lane7;
        ax[mt] = mrow & 63;
        aly[mt] = mrow >> 6;            // 0..3
    }
    const int brow = ((l >> 4) & 1) * 8 + lane7;
    const int bcb = (l >> 3) & 1;

#pragma unroll
    for (int tap = 0; tap < 9; tap++) {
        const int dy = tap / 3 - 1;
        const int dx = tap % 3 - 1;
        uint32_t abase[2];
        int akey[2];
#pragma unroll
        for (int mt = 0; mt < 2; mt++) {
            int p = (aly[mt] + dy + 1) * 66 + ax[mt] + dx + 1;
            akey[mt] = p & 7;
            abase[mt] = sb + p * 128;
        }
        const uint32_t btap = sb + C2_B + tap * 2048;
#pragma unroll
        for (int kb = 0; kb < 4; kb++) {
            uint32_t ah[2][4];
#pragma unroll
            for (int mt = 0; mt < 2; mt++) {
                int chunk = kb * 2 + hi16;
                ldsm4(ah[mt], abase[mt] + (uint32_t)((chunk ^ akey[mt]) << 4));
            }
            {
                int n = brow;
                uint32_t baddr = btap + n * 128 +
                                 (uint32_t)((((kb * 2 + bcb) ^ (n & 7))) << 4);
                uint32_t bh[4];
                ldsm4(bh, baddr);
#pragma unroll
                for (int mt = 0; mt < 2; mt++) {
                    mma16816h(d[mt][0], ah[mt], bh);
                    mma16816h(d[mt][1], ah[mt], bh + 2);
                }
            }
        }
    }

    // epilogue: bias + sigmoid -> attn NCHW fp32 (straight into d_out)
    const int lr = l >> 2;
    const int lc = (l & 3) * 2;
#pragma unroll
    for (int mt = 0; mt < 2; mt++) {
#pragma unroll
        for (int nb = 0; nb < 2; nb++) {
#pragma unroll
            for (int j = 0; j < 4; j++) {
                int n = nb * 8 + lc + (j & 1);
                int m = w8 * 32 + mt * 16 + lr + ((j >> 1) * 8);
                float v = d[mt][nb][j] + *(const float*)(smem + C2_BIAS + n * 4);
                v = 1.f / (1.f + __expf(-v));
                attn[((long)(b * 16 + n)) * 4096 + y0 * 64 + m] = v;
            }
        }
    }
}

// ---------------------------------------------------------------------------
// fuse: cs-GEMM fp16 (state x c3_w) + relu-reduction, atomicAdd into d_out.
// block = (b, 128-pixel chunk); 256 threads, warp tile 32x32.
// ---------------------------------------------------------------------------
#define F_A  0                   /* 16384 */
#define F_B  16384               /* 8192 */
#define F_CS 24576               /* 128 x 68 fp32 = 34816 */
#define F_ATT 59392              /* 16 x 128 fp32 = 8192 */
#define FUSE_SMEM 67584

__global__ __launch_bounds__(256) void fuse_kernel(
    const float* __restrict__ attn, const float* __restrict__ c3_b,
    float* __restrict__ out)
{
    extern __shared__ char smem[];
    const uint32_t sb = smem_u32(smem);
    float* cs_s = (float*)(smem + F_CS);
    float* attn_s = (float*)(smem + F_ATT);

    const int tid = threadIdx.x;
    const int w8 = tid >> 5;
    const int wm = w8 & 3;
    const int wn = w8 >> 2;
    const int l = tid & 31;
    const int b = blockIdx.x >> 5;
    const int chunk = blockIdx.x & 31;
    const int pbase = chunk * 128;

    // stage A (128 pixels of state fp16, swizzled), B (c3_w), attn
    {
        const uint8_t* srca = (const uint8_t*)g_x1 + ((long)b * 4096 + pbase) * 128;
#pragma unroll
        for (int i = 0; i < 4; i++) {
            int idx = tid + i * 256;       // (pp, q), 1024 units
            int pp = idx >> 3, q = idx & 7;
            uint32_t sw = (uint32_t)(pp * 128 + ((q ^ (pp & 7)) << 4));
            cp16(sb + F_A + sw, srca + idx * 16);
        }
#pragma unroll
        for (int i = 0; i < 2; i++) {
            int idx = tid + i * 256;       // 512 units
            cp16(sb + F_B + idx * 16, g_wt3 + idx * 16);
        }
#pragma unroll
        for (int i = 0; i < 2; i++) {
            int idx = tid + i * 256;       // (e, pp/4), 512 units
            int e = idx >> 5, p4 = idx & 31;
            cp16(sb + F_ATT + idx * 16,
                 attn + ((long)b * 16 + e) * HW + pbase + p4 * 4);
        }
        cp_commit();
        cp_wait<0>();
        __syncthreads();
    }

    // cs-GEMM: D[128 pix][64 o] fp16 single-term
    float d[2][4][4];
#pragma unroll
    for (int mt = 0; mt < 2; mt++)
#pragma unroll
        for (int nb = 0; nb < 4; nb++)
#pragma unroll
            for (int j = 0; j < 4; j++) d[mt][nb][j] = 0.f;

    const int lane7 = l & 7;
    const int hi16 = (l >> 4) & 1;
    const int brow = ((l >> 4) & 1) * 8 + lane7;
    const int bcb = (l >> 3) & 1;

#pragma unroll
    for (int kb = 0; kb < 4; kb++) {
        uint32_t ah[2][4];
#pragma unroll
        for (int mt = 0; mt < 2; mt++) {
            int pp = wm * 32 + mt * 16 + (l & 8) + lane7;
            int chunkq = kb * 2 + hi16;
            uint32_t sw = (uint32_t)(pp * 128 + ((chunkq ^ (pp & 7)) << 4));
            ldsm4(ah[mt], sb + F_A + sw);
        }
#pragma unroll
        for (int nbl = 0; nbl < 2; nbl++) {
            int nbp = wn * 2 + nbl;
            int n = nbp * 16 + brow;
            uint32_t baddr = sb + F_B + n * 128 +
                             (uint32_t)((((kb * 2 + bcb) ^ (n & 7))) << 4);
            uint32_t bh[4];
            ldsm4(bh, baddr);
#pragma unroll
            for (int mt = 0; mt < 2; mt++) {
                mma16816h(d[mt][2 * nbl], ah[mt], bh);
                mma16816h(d[mt][2 * nbl + 1], ah[mt], bh + 2);
            }
        }
    }

    // write cs fragments to smem [pp][o] pitch 68
    {
        const int lr = l >> 2;
        const int lc = (l & 3) * 2;
#pragma unroll
        for (int mt = 0; mt < 2; mt++) {
#pragma unroll
            for (int nbl = 0; nbl < 4; nbl++) {
                int nb = wn * 4 + nbl;
#pragma unroll
                for (int row = 0; row < 2; row++) {
                    int m = wm * 32 + mt * 16 + lr + row * 8;
                    int n = nb * 8 + lc;
                    float2 v = make_float2(d[mt][nbl][row * 2 + 0],
                                           d[mt][nbl][row * 2 + 1]);
                    *(float2*)(cs_s + m * 68 + n) = v;
                }
            }
        }
    }
    __syncthreads();

    // relu-reduction: thread (e, oq) sums 4 o's over 128 pixels, atomicAdd out
    {
        const int e = tid >> 4;
        const int oq = tid & 15;
        const float4 bias = ((const float4*)c3_b)[oq];
        float4 acc = make_float4(0.f, 0.f, 0.f, 0.f);
        const float* arow = attn_s + e * 128;
#pragma unroll 4
        for (int pp = 0; pp < 128; pp++) {
            float a = arow[pp];
            float4 cv = *(const float4*)(cs_s + pp * 68 + oq * 4);
            acc.x += fmaxf(fmaf(a, cv.x, bias.x), 0.f);
            acc.y += fmaxf(fmaf(a, cv.y, bias.y), 0.f);
            acc.z += fmaxf(fmaf(a, cv.z, bias.z), 0.f);
            acc.w += fmaxf(fmaf(a, cv.w, bias.w), 0.f);
        }
        float* po = out + (long)b * 1024 + e * 64 + oq * 4;
        const float s = 1.f / 4356.f;
        atomicAdd(po + 0, acc.x * s);
        atomicAdd(po + 1, acc.y * s);
        atomicAdd(po + 2, acc.z * s);
        atomicAdd(po + 3, acc.w * s);
    }
}

// ---------------------------------------------------------------------------
extern "C" void kernel_launch(void* const* d_in, const int* in_sizes, int n_in,
                              void* d_out, int out_size)
{
    const float* state = (const float*)d_in[0];
    const float* pre_w = (const float*)d_in[1];
    const float* pre_b = (const float*)d_in[2];
    const float* attn_w = (const float*)d_in[3];
    const float* attn_b = (const float*)d_in[4];
    const float* c3_w = (const float*)d_in[5];
    const float* c3_b = (const float*)d_in[6];

    float* out = (float*)d_out;
    float* attn = out + Bn * Ec * Fc;

    cudaFuncSetAttribute(fuse_kernel, cudaFuncAttributeMaxDynamicSharedMemorySize,
                         FUSE_SMEM);
    cudaFuncSetAttribute(conv1_mma_kernel, cudaFuncAttributeMaxDynamicSharedMemorySize,
                         CONV1_SMEM);
    cudaFuncSetAttribute(conv2_mma_kernel, cudaFuncAttributeMaxDynamicSharedMemorySize,
                         CONV2_SMEM);

    // prep: weights + out pad-term init + state fp16
    wprep_all_kernel<<<162, 256>>>(pre_w, attn_w, c3_w, c3_b, out);
    xprep_kernel<<<Bn * 64, 256>>>(state);
    // conv1: fp16 HMMA, async halo+B staging, 4 CTAs/SM
    conv1_mma_kernel<<<Bn * 32, 256, CONV1_SMEM>>>(pre_b);
    // conv2: fp16 HMMA, 4-row strips, async staging, 3 CTAs/SM
    conv2_mma_kernel<<<Bn * 16, 256, CONV2_SMEM>>>(attn_b, attn);
    // fuse: cs-GEMM fp16 + relu-reduction, atomicAdd into out
    fuse_kernel<<<Bn * 32, 256, FUSE_SMEM>>>(attn, c3_b, out);
}

// round 16
// speedup vs baseline: 2.0211x; 1.0519x over previous
#include <cuda_runtime.h>
#include <cuda_bf16.h>
#include <cuda_fp16.h>
#include <cstdint>

// Problem constants
#define Bn 16
#define Fc 64
#define Ec 16
#define Hh 64
#define Ww 64
#define HW (Hh * Ww)

// Scratch (device globals: allocation-free rule)
__device__ __align__(16) uint32_t g_x1[Bn * HW * 32];    // state fp16 [b][pix][ci2]
__device__ __align__(16) uint32_t g_x2[Bn * HW * 32];    // relu(conv1) fp16 [b][pix][ci2]
__device__ __align__(16) uint8_t  g_wt1[9 * 8192];       // conv1 W fp16 swizzled [tap][co][ci]
__device__ __align__(16) uint8_t  g_wt2[9 * 2048];       // conv2 W fp16 swizzled
__device__ __align__(16) uint8_t  g_wt3[8192];           // c3_w fp16 swizzled [o][f]

// ---------------------------------------------------------------------------
// mma.sync + ldmatrix + cp.async (baseline PTX, legal at compute_103)
// ---------------------------------------------------------------------------
__device__ __forceinline__ void mma16816h(float* d, const uint32_t* a, const uint32_t* b)
{
    asm volatile(
        "mma.sync.aligned.m16n8k16.row.col.f32.f16.f16.f32 "
        "{%0,%1,%2,%3}, {%4,%5,%6,%7}, {%8,%9}, {%0,%1,%2,%3};"
        : "+f"(d[0]), "+f"(d[1]), "+f"(d[2]), "+f"(d[3])
        : "r"(a[0]), "r"(a[1]), "r"(a[2]), "r"(a[3]), "r"(b[0]), "r"(b[1]));
}

__device__ __forceinline__ void ldsm4(uint32_t* r, uint32_t addr)
{
    asm volatile("ldmatrix.sync.aligned.m8n8.x4.shared.b16 {%0,%1,%2,%3}, [%4];"
                 : "=r"(r[0]), "=r"(r[1]), "=r"(r[2]), "=r"(r[3]) : "r"(addr));
}

__device__ __forceinline__ void cp16(uint32_t dst, const void* src)
{
    asm volatile("cp.async.cg.shared.global [%0], [%1], 16;" :: "r"(dst), "l"(src));
}
// cp.async with zero-fill when sz == 0 (CUTLASS zfill idiom)
__device__ __forceinline__ void cp16z(uint32_t dst, const void* src, int sz)
{
    asm volatile("cp.async.cg.shared.global [%0], [%1], 16, %2;"
                 :: "r"(dst), "l"(src), "r"(sz));
}
__device__ __forceinline__ void cp_commit()
{
    asm volatile("cp.async.commit_group;" ::: "memory");
}
template <int N>
__device__ __forceinline__ void cp_wait()
{
    asm volatile("cp.async.wait_group %0;" :: "n"(N) : "memory");
}

__device__ __forceinline__ uint32_t smem_u32(const void* p)
{
    uint32_t a;
    asm("{ .reg .u64 t; cvta.to.shared.u64 t, %1; cvt.u32.u64 %0, t; }" : "=r"(a) : "l"(p));
    return a;
}

__device__ __forceinline__ uint32_t pack_f16x2(float v0, float v1)
{
    __half2 h = __floats2half2_rn(v0, v1);
    return *(uint32_t*)&h;
}

// ---------------------------------------------------------------------------
// prep: state fp32 -> fp16 pixel-major (blocks 0..1023) + weight prep +
// d_out pad-term init (blocks 1024..1185).
// ---------------------------------------------------------------------------
__global__ __launch_bounds__(256) void prep_kernel(
    const float* __restrict__ state,
    const float* __restrict__ w1, const float* __restrict__ w2,
    const float* __restrict__ w3, const float* __restrict__ c3_b,
    float* __restrict__ out)
{
    int bi = blockIdx.x;
    int tid = threadIdx.x;
    if (bi < 1024) {
        __shared__ float s[64 * 65];
        int b = bi >> 6, y = bi & 63;
#pragma unroll
        for (int k = 0; k < 16; k++) {
            int idx = tid + k * 256;
            int ci = idx >> 6, x = idx & 63;
            s[ci * 65 + x] = state[((long)(b * 64 + ci) * 64 + y) * 64 + x];
        }
        __syncthreads();
#pragma unroll
        for (int k = 0; k < 8; k++) {
            int idx = tid + k * 256;
            int x = idx >> 5, j = idx & 31;
            float v0 = s[(2 * j) * 65 + x];
            float v1 = s[(2 * j + 1) * 65 + x];
            g_x1[((long)b * 4096 + y * 64 + x) * 32 + j] = pack_f16x2(v0, v1);
        }
        return;
    }
    int bj = bi - 1024;
    if (bj < 72) {
        int idx = bj * 256 + tid;                  // (tap, co64, ci-pair)
        int tap = idx >> 11;
        int rem = idx & 2047;
        int co = rem >> 5, ci2 = rem & 31;
        float v0 = w1[(co * 64 + 2 * ci2) * 9 + tap];
        float v1 = w1[(co * 64 + 2 * ci2 + 1) * 9 + tap];
        int q = ci2 >> 2, wd = ci2 & 3;
        int sw = ((q ^ (co & 7)) << 4) + wd * 4;
        *(uint32_t*)(g_wt1 + tap * 8192 + co * 128 + sw) = pack_f16x2(v0, v1);
    } else if (bj < 90) {
        int idx = (bj - 72) * 256 + tid;           // (tap, co16, ci-pair)
        if (idx >= 9 * 512) return;
        int tap = idx >> 9;
        int rem = idx & 511;
        int co = rem >> 5, ci2 = rem & 31;
        float v0 = w2[(co * 64 + 2 * ci2) * 9 + tap];
        float v1 = w2[(co * 64 + 2 * ci2 + 1) * 9 + tap];
        int q = ci2 >> 2, wd = ci2 & 3;
        int sw = ((q ^ (co & 7)) << 4) + wd * 4;
        *(uint32_t*)(g_wt2 + tap * 2048 + co * 128 + sw) = pack_f16x2(v0, v1);
    } else if (bj < 98) {
        int idx = (bj - 90) * 256 + tid;           // (o64, f-pair)
        if (idx >= 2048) return;
        int o = idx >> 5, f2 = idx & 31;
        float v0 = w3[o * 64 + 2 * f2];
        float v1 = w3[o * 64 + 2 * f2 + 1];
        int q = f2 >> 2, wd = f2 & 3;
        int sw = ((q ^ (o & 7)) << 4) + wd * 4;
        *(uint32_t*)(g_wt3 + o * 128 + sw) = pack_f16x2(v0, v1);
    } else {
        // out[b][e][o] init with pad term: 260*relu(c3_b[o]) / 4356
        int gid = (bj - 98) * 256 + tid;           // 0..16383
        int o = gid & 63;
        out[gid] = 260.f * fmaxf(c3_b[o], 0.f) * (1.f / 4356.f);
    }
}

// ---------------------------------------------------------------------------
// Smem layouts
// ---------------------------------------------------------------------------
// conv1 (2-row strip): halo 4x66 px + ALL 9 B taps + bias (sync-free mainloop)
#define AHALO4 264
#define C1_B 33792
#define C1_BIAS (C1_B + 73728)                 /* 107520 */
#define CONV1_SMEM (C1_BIAS + 256)             /* 107776 -> 2 CTAs/SM */
// conv2 (4-row strip): halo 6x66 px + B 9*2048 + bias
#define AHALO6 396
#define C2_B 50688
#define C2_BIAS (C2_B + 18432)                 /* 69120 */
#define CONV2_SMEM (C2_BIAS + 64)              /* 69184 */

// fp16 halo stage via cp.async + zfill; issues only, caller commits/waits.
template <int NT, int NPIX>
__device__ __forceinline__ void stage_halo_async(
    uint32_t sb_halo, const uint8_t* x, int b, int y0, int tid)
{
    for (int p = tid; p < NPIX; p += NT) {
        int r = p / 66, c = p - r * 66;
        int y = y0 - 1 + r;
        int xx = c - 1;
        bool ok = ((unsigned)y < 64u) && ((unsigned)xx < 64u);
        const uint8_t* src = ok ? x + ((long)b * 4096 + y * 64 + xx) * 128 : x;
        int sz = ok ? 16 : 0;
        uint32_t dst = sb_halo + p * 128;
        int key = p & 7;
#pragma unroll
        for (int q = 0; q < 8; q++)
            cp16z(dst + ((q ^ key) << 4), src + q * 16, sz);
    }
}

// ---------------------------------------------------------------------------
// conv1: fp16; 256 threads, 8 warps (wm x wn), warp tile 32x32, 2-row strip.
// ALL B taps + halo staged upfront in ONE cp.async group -> zero mainloop
// syncs. 2 CTAs/SM. Epilogue relu -> fp16 x.
// ---------------------------------------------------------------------------
__global__ __launch_bounds__(256) void conv1_mma_kernel(const float* __restrict__ bias)
{
    extern __shared__ char smem[];
    const uint32_t sb = smem_u32(smem);
    const int tid = threadIdx.x;
    const int w8 = tid >> 5;
    const int wm = w8 & 3;
    const int wn = w8 >> 2;
    const int l = tid & 31;
    const int b = blockIdx.x >> 5;
    const int y0 = (blockIdx.x & 31) * 2;

    if (tid < 64) *(float*)(smem + C1_BIAS + tid * 4) = bias[tid];

    // stage all 9 B taps (4608 uint4) + halo, async, one group
#pragma unroll
    for (int i = 0; i < 18; i++) {
        int idx = tid + i * 256;
        cp16(sb + C1_B + idx * 16, g_wt1 + idx * 16);
    }
    stage_halo_async<256, AHALO4>(sb, (const uint8_t*)g_x1, b, y0, tid);
    cp_commit();
    cp_wait<0>();
    __syncthreads();

    float d[2][4][4];
#pragma unroll
    for (int mt = 0; mt < 2; mt++)
#pragma unroll
        for (int nb = 0; nb < 4; nb++)
#pragma unroll
            for (int j = 0; j < 4; j++) d[mt][nb][j] = 0.f;

    const int lane7 = l & 7;
    const int hi16 = (l >> 4) & 1;
    int ax[2], aly[2];
#pragma unroll
    for (int mt = 0; mt < 2; mt++) {
        int mrow = wm * 32 + mt * 16 + (l & 8) + lane7;
        ax[mt] = mrow & 63;
        aly[mt] = mrow >> 6;
    }
    const int brow = ((l >> 4) & 1) * 8 + lane7;
    const int bcb = (l >> 3) & 1;

#pragma unroll
    for (int tap = 0; tap < 9; tap++) {
        const int dy = tap / 3 - 1;
        const int dx = tap % 3 - 1;
        uint32_t abase[2];
        int akey[2];
#pragma unroll
        for (int mt = 0; mt < 2; mt++) {
            int p = (aly[mt] + dy + 1) * 66 + ax[mt] + dx + 1;
            akey[mt] = p & 7;
            abase[mt] = sb + p * 128;
        }
        const uint32_t btap = sb + C1_B + tap * 8192;
#pragma unroll
        for (int kb = 0; kb < 4; kb++) {
            uint32_t ah[2][4];
#pragma unroll
            for (int mt = 0; mt < 2; mt++) {
                int chunk = kb * 2 + hi16;
                ldsm4(ah[mt], abase[mt] + (uint32_t)((chunk ^ akey[mt]) << 4));
            }
#pragma unroll
            for (int nbl = 0; nbl < 2; nbl++) {
                int nbp = wn * 2 + nbl;
                int n = nbp * 16 + brow;
                uint32_t baddr = btap + n * 128 +
                                 (uint32_t)((((kb * 2 + bcb) ^ (n & 7))) << 4);
                uint32_t bh[4];
                ldsm4(bh, baddr);
#pragma unroll
                for (int mt = 0; mt < 2; mt++) {
                    mma16816h(d[mt][2 * nbl], ah[mt], bh);
                    mma16816h(d[mt][2 * nbl + 1], ah[mt], bh + 2);
                }
            }
        }
    }

    // epilogue: bias+relu -> fp16 pixel-major [b][pix][ci2]
    const int lr = l >> 2;
    const int lc2 = l & 3;
#pragma unroll
    for (int mt = 0; mt < 2; mt++) {
#pragma unroll
        for (int nbl = 0; nbl < 4; nbl++) {
            int nb = wn * 4 + nbl;
            float b0 = *(const float*)(smem + C1_BIAS + (nb * 8 + lc2 * 2) * 4);
            float b1 = *(const float*)(smem + C1_BIAS + (nb * 8 + lc2 * 2 + 1) * 4);
#pragma unroll
            for (int row = 0; row < 2; row++) {
                int m = wm * 32 + mt * 16 + lr + row * 8;
                float v0 = fmaxf(d[mt][nbl][row * 2 + 0] + b0, 0.f);
                float v1 = fmaxf(d[mt][nbl][row * 2 + 1] + b1, 0.f);
                long o = ((long)b * 4096 + y0 * 64 + m) * 32 + nb * 4 + lc2;
                g_x2[o] = pack_f16x2(v0, v1);
            }
        }
    }
}

// ---------------------------------------------------------------------------
// conv2: fp16; 4-row strip (M=256), 256 threads, warp tile 32x16; 3 CTAs/SM.
// All staging via cp.async (B + halo, one group). Sigmoid into d_out.
// ---------------------------------------------------------------------------
__global__ __launch_bounds__(256) void conv2_mma_kernel(
    const float* __restrict__ bias, float* __restrict__ attn)
{
    extern __shared__ char smem[];
    const uint32_t sb = smem_u32(smem);
    const int tid = threadIdx.x;
    const int w8 = tid >> 5;
    const int l = tid & 31;
    const int b = blockIdx.x >> 4;
    const int y0 = (blockIdx.x & 15) * 4;

    if (tid < 16) *(float*)(smem + C2_BIAS + tid * 4) = bias[tid];

    // stage all 9 B tiles (1152 uint4) + halo, async, one group
#pragma unroll
    for (int i = 0; i < 5; i++) {
        int idx = tid + i * 256;
        if (idx < 1152) cp16(sb + C2_B + idx * 16, g_wt2 + idx * 16);
    }
    stage_halo_async<256, AHALO6>(sb, (const uint8_t*)g_x2, b, y0, tid);
    cp_commit();
    cp_wait<0>();
    __syncthreads();

    float d[2][2][4];
#pragma unroll
    for (int mt = 0; mt < 2; mt++)
#pragma unroll
        for (int nb = 0; nb < 2; nb++)
#pragma unroll
            for (int j = 0; j < 4; j++) d[mt][nb][j] = 0.f;

    const int lane7 = l & 7;
    const int hi16 = (l >> 4) & 1;
    int ax[2], aly[2];
#pragma unroll
    for (int mt = 0; mt < 2; mt++) {
        int mrow = w8 * 32 + mt * 16 + (l & 8) + lane7;
        ax[mt] = mrow & 63;
        aly[mt] = mrow >> 6;            // 0..3
    }
    const int brow = ((l >> 4) & 1) * 8 + lane7;
    const int bcb = (l >> 3) & 1;

#pragma unroll
    for (int tap = 0; tap < 9; tap++) {
        const int dy = tap / 3 - 1;
        const int dx = tap % 3 - 1;
        uint32_t abase[2];
        int akey[2];
#pragma unroll
        for (int mt = 0; mt < 2; mt++) {
            int p = (aly[mt] + dy + 1) * 66 + ax[mt] + dx + 1;
            akey[mt] = p & 7;
            abase[mt] = sb + p * 128;
        }
        const uint32_t btap = sb + C2_B + tap * 2048;
#pragma unroll
        for (int kb = 0; kb < 4; kb++) {
            uint32_t ah[2][4];
#pragma unroll
            for (int mt = 0; mt < 2; mt++) {
                int chunk = kb * 2 + hi16;
                ldsm4(ah[mt], abase[mt] + (uint32_t)((chunk ^ akey[mt]) << 4));
            }
            {
                int n = brow;
                uint32_t baddr = btap + n * 128 +
                                 (uint32_t)((((kb * 2 + bcb) ^ (n & 7))) << 4);
                uint32_t bh[4];
                ldsm4(bh, baddr);
#pragma unroll
                for (int mt = 0; mt < 2; mt++) {
                    mma16816h(d[mt][0], ah[mt], bh);
                    mma16816h(d[mt][1], ah[mt], bh + 2);
                }
            }
        }
    }

    // epilogue: bias + sigmoid -> attn NCHW fp32 (straight into d_out)
    const int lr = l >> 2;
    const int lc = (l & 3) * 2;
#pragma unroll
    for (int mt = 0; mt < 2; mt++) {
#pragma unroll
        for (int nb = 0; nb < 2; nb++) {
#pragma unroll
            for (int j = 0; j < 4; j++) {
                int n = nb * 8 + lc + (j & 1);
                int m = w8 * 32 + mt * 16 + lr + ((j >> 1) * 8);
                float v = d[mt][nb][j] + *(const float*)(smem + C2_BIAS + n * 4);
                v = 1.f / (1.f + __expf(-v));
                attn[((long)(b * 16 + n)) * 4096 + y0 * 64 + m] = v;
            }
        }
    }
}

// ---------------------------------------------------------------------------
// fuse: cs-GEMM fp16 (state x c3_w) + relu-reduction, atomicAdd into d_out.
// block = (b, 128-pixel chunk); 256 threads, warp tile 32x32.
// ---------------------------------------------------------------------------
#define F_A  0                   /* 16384 */
#define F_B  16384               /* 8192 */
#define F_CS 24576               /* 128 x 68 fp32 = 34816 */
#define F_ATT 59392              /* 16 x 128 fp32 = 8192 */
#define FUSE_SMEM 67584

__global__ __launch_bounds__(256) void fuse_kernel(
    const float* __restrict__ attn, const float* __restrict__ c3_b,
    float* __restrict__ out)
{
    extern __shared__ char smem[];
    const uint32_t sb = smem_u32(smem);
    float* cs_s = (float*)(smem + F_CS);
    float* attn_s = (float*)(smem + F_ATT);

    const int tid = threadIdx.x;
    const int w8 = tid >> 5;
    const int wm = w8 & 3;
    const int wn = w8 >> 2;
    const int l = tid & 31;
    const int b = blockIdx.x >> 5;
    const int chunk = blockIdx.x & 31;
    const int pbase = chunk * 128;

    // stage A (128 pixels of state fp16, swizzled), B (c3_w), attn
    {
        const uint8_t* srca = (const uint8_t*)g_x1 + ((long)b * 4096 + pbase) * 128;
#pragma unroll
        for (int i = 0; i < 4; i++) {
            int idx = tid + i * 256;       // (pp, q), 1024 units
            int pp = idx >> 3, q = idx & 7;
            uint32_t sw = (uint32_t)(pp * 128 + ((q ^ (pp & 7)) << 4));
            cp16(sb + F_A + sw, srca + idx * 16);
        }
#pragma unroll
        for (int i = 0; i < 2; i++) {
            int idx = tid + i * 256;       // 512 units
            cp16(sb + F_B + idx * 16, g_wt3 + idx * 16);
        }
#pragma unroll
        for (int i = 0; i < 2; i++) {
            int idx = tid + i * 256;       // (e, pp/4), 512 units
            int e = idx >> 5, p4 = idx & 31;
            cp16(sb + F_ATT + idx * 16,
                 attn + ((long)b * 16 + e) * HW + pbase + p4 * 4);
        }
        cp_commit();
        cp_wait<0>();
        __syncthreads();
    }

    // cs-GEMM: D[128 pix][64 o] fp16 single-term
    float d[2][4][4];
#pragma unroll
    for (int mt = 0; mt < 2; mt++)
#pragma unroll
        for (int nb = 0; nb < 4; nb++)
#pragma unroll
            for (int j = 0; j < 4; j++) d[mt][nb][j] = 0.f;

    const int lane7 = l & 7;
    const int hi16 = (l >> 4) & 1;
    const int brow = ((l >> 4) & 1) * 8 + lane7;
    const int bcb = (l >> 3) & 1;

#pragma unroll
    for (int kb = 0; kb < 4; kb++) {
        uint32_t ah[2][4];
#pragma unroll
        for (int mt = 0; mt < 2; mt++) {
            int pp = wm * 32 + mt * 16 + (l & 8) + lane7;
            int chunkq = kb * 2 + hi16;
            uint32_t sw = (uint32_t)(pp * 128 + ((chunkq ^ (pp & 7)) << 4));
            ldsm4(ah[mt], sb + F_A + sw);
        }
#pragma unroll
        for (int nbl = 0; nbl < 2; nbl++) {
            int nbp = wn * 2 + nbl;
            int n = nbp * 16 + brow;
            uint32_t baddr = sb + F_B + n * 128 +
                             (uint32_t)((((kb * 2 + bcb) ^ (n & 7))) << 4);
            uint32_t bh[4];
            ldsm4(bh, baddr);
#pragma unroll
            for (int mt = 0; mt < 2; mt++) {
                mma16816h(d[mt][2 * nbl], ah[mt], bh);
                mma16816h(d[mt][2 * nbl + 1], ah[mt], bh + 2);
            }
        }
    }

    // write cs fragments to smem [pp][o] pitch 68
    {
        const int lr = l >> 2;
        const int lc = (l & 3) * 2;
#pragma unroll
        for (int mt = 0; mt < 2; mt++) {
#pragma unroll
            for (int nbl = 0; nbl < 4; nbl++) {
                int nb = wn * 4 + nbl;
#pragma unroll
                for (int row = 0; row < 2; row++) {
                    int m = wm * 32 + mt * 16 + lr + row * 8;
                    int n = nb * 8 + lc;
                    float2 v = make_float2(d[mt][nbl][row * 2 + 0],
                                           d[mt][nbl][row * 2 + 1]);
                    *(float2*)(cs_s + m * 68 + n) = v;
                }
            }
        }
    }
    __syncthreads();

    // relu-reduction: thread (e, oq) sums 4 o's over 128 pixels, atomicAdd out
    {
        const int e = tid >> 4;
        const int oq = tid & 15;
        const float4 bias = ((const float4*)c3_b)[oq];
        float4 acc = make_float4(0.f, 0.f, 0.f, 0.f);
        const float* arow = attn_s + e * 128;
#pragma unroll 4
        for (int pp = 0; pp < 128; pp++) {
            float a = arow[pp];
            float4 cv = *(const float4*)(cs_s + pp * 68 + oq * 4);
            acc.x += fmaxf(fmaf(a, cv.x, bias.x), 0.f);
            acc.y += fmaxf(fmaf(a, cv.y, bias.y), 0.f);
            acc.z += fmaxf(fmaf(a, cv.z, bias.z), 0.f);
            acc.w += fmaxf(fmaf(a, cv.w, bias.w), 0.f);
        }
        float* po = out + (long)b * 1024 + e * 64 + oq * 4;
        const float s = 1.f / 4356.f;
        atomicAdd(po + 0, acc.x * s);
        atomicAdd(po + 1, acc.y * s);
        atomicAdd(po + 2, acc.z * s);
        atomicAdd(po + 3, acc.w * s);
    }
}

// ---------------------------------------------------------------------------
extern "C" void kernel_launch(void* const* d_in, const int* in_sizes, int n_in,
                              void* d_out, int out_size)
{
    const float* state = (const float*)d_in[0];
    const float* pre_w = (const float*)d_in[1];
    const float* pre_b = (const float*)d_in[2];
    const float* attn_w = (const float*)d_in[3];
    const float* attn_b = (const float*)d_in[4];
    const float* c3_w = (const float*)d_in[5];
    const float* c3_b = (const float*)d_in[6];

    float* out = (float*)d_out;
    float* attn = out + Bn * Ec * Fc;

    cudaFuncSetAttribute(fuse_kernel, cudaFuncAttributeMaxDynamicSharedMemorySize,
                         FUSE_SMEM);
    cudaFuncSetAttribute(conv1_mma_kernel, cudaFuncAttributeMaxDynamicSharedMemorySize,
                         CONV1_SMEM);
    cudaFuncSetAttribute(conv2_mma_kernel, cudaFuncAttributeMaxDynamicSharedMemorySize,
                         CONV2_SMEM);

    // prep: state fp16 + weights + out pad-term init (one kernel)
    prep_kernel<<<1186, 256>>>(state, pre_w, attn_w, c3_w, c3_b, out);
    // conv1: fp16 HMMA, all-B-upfront sync-free mainloop, 2 CTAs/SM
    conv1_mma_kernel<<<Bn * 32, 256, CONV1_SMEM>>>(pre_b);
    // conv2: fp16 HMMA, 4-row strips, async staging, 3 CTAs/SM
    conv2_mma_kernel<<<Bn * 16, 256, CONV2_SMEM>>>(attn_b, attn);
    // fuse: cs-GEMM fp16 + relu-reduction, atomicAdd into out
    fuse_kernel<<<Bn * 32, 256, FUSE_SMEM>>>(attn, c3_b, out);
}